// round 1
// baseline (speedup 1.0000x reference)
#include <cuda_runtime.h>
#include <cstdint>
#include <math.h>

// Problem constants
#define D_MODEL 1024
#define S_LEN   4096
#define BATCH   4
#define NEXP    4
#define NTOK    16384          // BATCH * S_LEN
#define CHUNK   64
#define NCHUNK  64             // S_LEN / CHUNK

// ---------------------------------------------------------------------------
// Scratch (device globals; no dynamic allocation allowed)
// ---------------------------------------------------------------------------
__device__ float g_xs[(size_t)NEXP * NTOK * D_MODEL];   // sigmoid(g)*tanh(v)  (256 MB)
__device__ float g_a [(size_t)NEXP * NTOK * D_MODEL];   // 0.001+0.998*sigm(d) (256 MB)
__device__ float g_sumA  [NEXP * BATCH * NCHUNK * D_MODEL];  // per-chunk prod(a)
__device__ float g_sumX  [NEXP * BATCH * NCHUNK * D_MODEL];  // per-chunk scanned X
__device__ float g_hstart[NEXP * BATCH * NCHUNK * D_MODEL];  // state entering chunk
__device__ float g_w[NTOK * NEXP];                           // router weights (0 if unselected)

// ---------------------------------------------------------------------------
// Helpers
// ---------------------------------------------------------------------------
__device__ __forceinline__ uint32_t f2tf32(float x) {
    uint32_t u;
    asm("cvt.rna.tf32.f32 %0, %1;" : "=r"(u) : "f"(x));
    return u;
}
__device__ __forceinline__ float sigmoidf_(float z) { return 1.0f / (1.0f + expf(-z)); }

__device__ __forceinline__ void mma_tf32(float* c, const uint32_t* a, const uint32_t* b) {
    asm volatile(
        "mma.sync.aligned.m16n8k8.row.col.f32.tf32.tf32.f32 "
        "{%0,%1,%2,%3}, {%4,%5,%6,%7}, {%8,%9}, {%0,%1,%2,%3};\n"
        : "+f"(c[0]), "+f"(c[1]), "+f"(c[2]), "+f"(c[3])
        : "r"(a[0]), "r"(a[1]), "r"(a[2]), "r"(a[3]), "r"(b[0]), "r"(b[1]));
}

// ---------------------------------------------------------------------------
// Router: gate logits (x @ Wgate^T), top-2, softmax -> dense weight vector w[4]
// One warp per token.
// ---------------------------------------------------------------------------
__global__ __launch_bounds__(256) void router_kernel(const float* __restrict__ x,
                                                     const float* __restrict__ Wgate) {
    int gtid  = blockIdx.x * 256 + threadIdx.x;
    int token = gtid >> 5;
    int lane  = gtid & 31;
    const float* xr = x + (size_t)token * D_MODEL;

    float a0 = 0.f, a1 = 0.f, a2 = 0.f, a3 = 0.f;
    #pragma unroll 8
    for (int k = lane; k < D_MODEL; k += 32) {
        float xv = xr[k];
        a0 = fmaf(xv, Wgate[k],               a0);
        a1 = fmaf(xv, Wgate[D_MODEL + k],     a1);
        a2 = fmaf(xv, Wgate[2 * D_MODEL + k], a2);
        a3 = fmaf(xv, Wgate[3 * D_MODEL + k], a3);
    }
    #pragma unroll
    for (int o = 16; o; o >>= 1) {
        a0 += __shfl_down_sync(0xffffffffu, a0, o);
        a1 += __shfl_down_sync(0xffffffffu, a1, o);
        a2 += __shfl_down_sync(0xffffffffu, a2, o);
        a3 += __shfl_down_sync(0xffffffffu, a3, o);
    }
    if (lane == 0) {
        float l[4] = {a0, a1, a2, a3};
        int i0 = 0;
        #pragma unroll
        for (int i = 1; i < 4; i++) if (l[i] > l[i0]) i0 = i;
        int i1 = -1;
        #pragma unroll
        for (int i = 0; i < 4; i++) if (i != i0 && (i1 < 0 || l[i] > l[i1])) i1 = i;
        float ex = expf(l[i1] - l[i0]);       // <= 1, stable
        float den = 1.0f + ex;
        float wv[4] = {0.f, 0.f, 0.f, 0.f};
        wv[i0] = 1.0f / den;
        wv[i1] = ex / den;
        float4 o4 = make_float4(wv[0], wv[1], wv[2], wv[3]);
        *(float4*)(g_w + (size_t)token * NEXP) = o4;
    }
}

// ---------------------------------------------------------------------------
// Fused projection GEMM (tf32 mma.sync):
//   per expert, per output tile computes g, v, d simultaneously (3 accumulators
//   sharing the A tile), applies activations in the epilogue, and writes
//   x_scan and a directly.
// CTA tile: 128(M) x 64(N), K-chunk 32. 8 warps: 4(M) x 2(N), warp tile 32x32.
// ---------------------------------------------------------------------------
#define BM 128
#define BN 64
#define BK 32

__global__ __launch_bounds__(256) void proj_gemm_kernel(
    const float* __restrict__ x,
    const float* __restrict__ Wg, const float* __restrict__ bg,
    const float* __restrict__ Wv, const float* __restrict__ bv,
    const float* __restrict__ Wd, const float* __restrict__ bd)
{
    const int e     = blockIdx.z;
    const int mBase = blockIdx.y * BM;
    const int nBase = blockIdx.x * BN;

    __shared__ uint32_t sA[BM][BK + 1];
    __shared__ uint32_t sB[3][BN][BK + 1];

    const float* Wmat[3] = {
        Wg + (size_t)e * D_MODEL * D_MODEL,
        Wv + (size_t)e * D_MODEL * D_MODEL,
        Wd + (size_t)e * D_MODEL * D_MODEL };

    const int tid  = threadIdx.x;
    const int wid  = tid >> 5, lane = tid & 31;
    const int wm   = wid >> 1, wn = wid & 1;       // warp grid 4(M) x 2(N)
    const int grp  = lane >> 2, qid = lane & 3;

    float acc[3][2][4][4];
    #pragma unroll
    for (int m = 0; m < 3; m++)
        #pragma unroll
        for (int i = 0; i < 2; i++)
            #pragma unroll
            for (int j = 0; j < 4; j++)
                #pragma unroll
                for (int r = 0; r < 4; r++) acc[m][i][j][r] = 0.f;

    const int lrow = tid >> 3;          // 0..31
    const int lc4  = (tid & 7) * 4;     // 0..28

    for (int kb = 0; kb < D_MODEL; kb += BK) {
        // ---- load A tile (128 x 32) ----
        #pragma unroll
        for (int r = 0; r < 4; r++) {
            int row = lrow + r * 32;
            float4 v = *(const float4*)(x + (size_t)(mBase + row) * D_MODEL + kb + lc4);
            sA[row][lc4 + 0] = f2tf32(v.x);
            sA[row][lc4 + 1] = f2tf32(v.y);
            sA[row][lc4 + 2] = f2tf32(v.z);
            sA[row][lc4 + 3] = f2tf32(v.w);
        }
        // ---- load 3 B tiles (64 x 32 each); W is (out,in) row-major = K-minor ----
        #pragma unroll
        for (int m = 0; m < 3; m++) {
            #pragma unroll
            for (int r = 0; r < 2; r++) {
                int row = lrow + r * 32;
                float4 v = *(const float4*)(Wmat[m] + (size_t)(nBase + row) * D_MODEL + kb + lc4);
                sB[m][row][lc4 + 0] = f2tf32(v.x);
                sB[m][row][lc4 + 1] = f2tf32(v.y);
                sB[m][row][lc4 + 2] = f2tf32(v.z);
                sB[m][row][lc4 + 3] = f2tf32(v.w);
            }
        }
        __syncthreads();

        #pragma unroll
        for (int k8 = 0; k8 < BK; k8 += 8) {
            uint32_t af[2][4];
            #pragma unroll
            for (int i = 0; i < 2; i++) {
                int r0 = wm * 32 + i * 16 + grp;
                af[i][0] = sA[r0    ][k8 + qid];
                af[i][1] = sA[r0 + 8][k8 + qid];
                af[i][2] = sA[r0    ][k8 + qid + 4];
                af[i][3] = sA[r0 + 8][k8 + qid + 4];
            }
            uint32_t bf[3][4][2];
            #pragma unroll
            for (int m = 0; m < 3; m++)
                #pragma unroll
                for (int j = 0; j < 4; j++) {
                    int n0 = wn * 32 + j * 8 + grp;
                    bf[m][j][0] = sB[m][n0][k8 + qid];
                    bf[m][j][1] = sB[m][n0][k8 + qid + 4];
                }
            #pragma unroll
            for (int m = 0; m < 3; m++)
                #pragma unroll
                for (int i = 0; i < 2; i++)
                    #pragma unroll
                    for (int j = 0; j < 4; j++)
                        mma_tf32(acc[m][i][j], af[i], bf[m][j]);
        }
        __syncthreads();
    }

    // ---- fused epilogue: bias + activations -> g_xs / g_a ----
    const float* bias0 = bg + e * D_MODEL;
    const float* bias1 = bv + e * D_MODEL;
    const float* bias2 = bd + e * D_MODEL;
    #pragma unroll
    for (int i = 0; i < 2; i++)
        #pragma unroll
        for (int j = 0; j < 4; j++)
            #pragma unroll
            for (int h = 0; h < 2; h++) {
                int row = mBase + wm * 32 + i * 16 + grp + h * 8;
                int col = nBase + wn * 32 + j * 8 + qid * 2;
                float g0 = acc[0][i][j][h * 2 + 0] + bias0[col];
                float g1 = acc[0][i][j][h * 2 + 1] + bias0[col + 1];
                float v0 = acc[1][i][j][h * 2 + 0] + bias1[col];
                float v1 = acc[1][i][j][h * 2 + 1] + bias1[col + 1];
                float d0 = acc[2][i][j][h * 2 + 0] + bias2[col];
                float d1 = acc[2][i][j][h * 2 + 1] + bias2[col + 1];
                float2 xs = make_float2(sigmoidf_(g0) * tanhf(v0),
                                        sigmoidf_(g1) * tanhf(v1));
                float2 av = make_float2(0.001f + 0.998f * sigmoidf_(d0),
                                        0.001f + 0.998f * sigmoidf_(d1));
                size_t base = ((size_t)e * NTOK + row) * D_MODEL + col;
                *(float2*)(g_xs + base) = xs;
                *(float2*)(g_a  + base) = av;
            }
}

// ---------------------------------------------------------------------------
// Chunked linear scan: h_t = a_t*h_{t-1} + x_t
// Pass 1: per-chunk summaries (A = prod a, X = chunk scan from 0)
// ---------------------------------------------------------------------------
__global__ __launch_bounds__(256) void scan_pass1() {
    int d  = blockIdx.x * 256 + threadIdx.x;
    int c  = blockIdx.y;
    int eb = blockIdx.z;            // e*BATCH + b
    size_t base = ((size_t)eb * S_LEN + c * CHUNK) * D_MODEL + d;
    float A = 1.f, X = 0.f;
    #pragma unroll 8
    for (int t = 0; t < CHUNK; t++) {
        float a  = g_a [base + (size_t)t * D_MODEL];
        float xv = g_xs[base + (size_t)t * D_MODEL];
        X = fmaf(a, X, xv);
        A *= a;
    }
    int sidx = (eb * NCHUNK + c) * D_MODEL + d;
    g_sumA[sidx] = A;
    g_sumX[sidx] = X;
}

// Pass 2: serial prefix over chunks per channel -> h entering each chunk
__global__ __launch_bounds__(256) void scan_pass2() {
    int idx = blockIdx.x * 256 + threadIdx.x;   // 0..16383 = eb*1024 + d
    int eb = idx >> 10, d = idx & 1023;
    float h = 0.f;
    for (int c = 0; c < NCHUNK; c++) {
        int s = (eb * NCHUNK + c) * D_MODEL + d;
        g_hstart[s] = h;
        h = fmaf(g_sumA[s], h, g_sumX[s]);
    }
}

// Pass 3: re-scan each chunk with correct start state for all 4 experts,
// fused with router combine: out[b,t,d] = sum_e w[b,t,e] * h_e
__global__ __launch_bounds__(256) void scan_pass3(float* __restrict__ out) {
    int d = blockIdx.x * 256 + threadIdx.x;
    int c = blockIdx.y;
    int b = blockIdx.z;
    __shared__ float ws[CHUNK * NEXP];   // 64 tokens x 4 experts = 256 floats
    int t0 = c * CHUNK;
    ws[threadIdx.x] = g_w[(size_t)(b * S_LEN + t0) * NEXP + threadIdx.x];
    __syncthreads();

    float  h[NEXP];
    size_t xbase[NEXP];
    #pragma unroll
    for (int e = 0; e < NEXP; e++) {
        int eb = e * BATCH + b;
        h[e]     = g_hstart[(eb * NCHUNK + c) * D_MODEL + d];
        xbase[e] = ((size_t)eb * S_LEN + t0) * D_MODEL + d;
    }
    float* op = out + ((size_t)(b * S_LEN + t0)) * D_MODEL + d;
    #pragma unroll 4
    for (int t = 0; t < CHUNK; t++) {
        float acc = 0.f;
        #pragma unroll
        for (int e = 0; e < NEXP; e++) {
            size_t idx = xbase[e] + (size_t)t * D_MODEL;
            h[e] = fmaf(g_a[idx], h[e], g_xs[idx]);
            acc  = fmaf(ws[t * NEXP + e], h[e], acc);
        }
        op[(size_t)t * D_MODEL] = acc;
    }
}

// ---------------------------------------------------------------------------
// Launch
// ---------------------------------------------------------------------------
extern "C" void kernel_launch(void* const* d_in, const int* in_sizes, int n_in,
                              void* d_out, int out_size) {
    const float* x     = (const float*)d_in[0];
    const float* Wg    = (const float*)d_in[1];
    const float* bg    = (const float*)d_in[2];
    const float* Wv    = (const float*)d_in[3];
    const float* bv    = (const float*)d_in[4];
    const float* Wd    = (const float*)d_in[5];
    const float* bd    = (const float*)d_in[6];
    const float* Wgate = (const float*)d_in[7];
    float* out = (float*)d_out;

    router_kernel<<<(NTOK * 32) / 256, 256>>>(x, Wgate);
    proj_gemm_kernel<<<dim3(D_MODEL / BN, NTOK / BM, NEXP), 256>>>(x, Wg, bg, Wv, bv, Wd, bd);
    scan_pass1<<<dim3(D_MODEL / 256, NCHUNK, NEXP * BATCH), 256>>>();
    scan_pass2<<<(NEXP * BATCH * D_MODEL) / 256, 256>>>();
    scan_pass3<<<dim3(D_MODEL / 256, NCHUNK, BATCH), 256>>>(out);
}

// round 2
// speedup vs baseline: 2.1249x; 2.1249x over previous
#include <cuda_runtime.h>
#include <cstdint>
#include <math.h>

// Problem constants
#define D_MODEL 1024
#define S_LEN   4096
#define BATCH   4
#define NEXP    4
#define NTOK    16384          // BATCH * S_LEN
#define CHUNK   64
#define NCHUNK  64             // S_LEN / CHUNK

// GEMM tiling
#define BM 128
#define BN 32
#define BK 32
#define PAD 4
#define AW (BK + PAD)                 // 36 floats per row (144B, 16B aligned)
#define A_STAGE (BM * AW)             // 4608 floats
#define B_STAGE (3 * BN * AW)         // 3456 floats
#define STAGE_FLOATS (A_STAGE + B_STAGE)   // 8064
#define SMEM_BYTES (2 * STAGE_FLOATS * 4)  // 64512 B

// ---------------------------------------------------------------------------
// Scratch (device globals; no dynamic allocation allowed)
// ---------------------------------------------------------------------------
__device__ float g_xs[(size_t)NEXP * NTOK * D_MODEL];   // sigmoid(g)*tanh(v)
__device__ float g_a [(size_t)NEXP * NTOK * D_MODEL];   // 0.001+0.998*sigm(d)
__device__ float g_sumA  [NEXP * BATCH * NCHUNK * D_MODEL];
__device__ float g_sumX  [NEXP * BATCH * NCHUNK * D_MODEL];
__device__ float g_hstart[NEXP * BATCH * NCHUNK * D_MODEL];
__device__ float g_w[NTOK * NEXP];

// ---------------------------------------------------------------------------
// Helpers
// ---------------------------------------------------------------------------
__device__ __forceinline__ uint32_t f2tf32(float x) {
    uint32_t u;
    asm("cvt.rna.tf32.f32 %0, %1;" : "=r"(u) : "f"(x));
    return u;
}
__device__ __forceinline__ float ex2f_(float x) {
    float y; asm("ex2.approx.f32 %0, %1;" : "=f"(y) : "f"(x)); return y;
}
// FMA-pipe reciprocal (x > 0, normal range): bit-trick seed + 3 Newton steps
__device__ __forceinline__ float frcp_(float x) {
    float y = __uint_as_float(0x7EF311C3u - __float_as_uint(x));
    y = y * (2.0f - x * y);
    y = y * (2.0f - x * y);
    y = y * (2.0f - x * y);
    return y;
}
__device__ __forceinline__ float sigmoid_acc(float z) {
    z = fminf(fmaxf(z, -30.0f), 30.0f);
    return frcp_(1.0f + ex2f_(-1.4426950408889634f * z));
}
__device__ __forceinline__ float tanh_acc(float v) {
    v = fminf(fmaxf(v, -9.0f), 9.0f);
    float t = ex2f_(2.8853900817779268f * v);      // e^{2v}
    return (t - 1.0f) * frcp_(t + 1.0f);
}

__device__ __forceinline__ void mma_tf32(float* c, const uint32_t* a, const uint32_t* b) {
    asm volatile(
        "mma.sync.aligned.m16n8k8.row.col.f32.tf32.tf32.f32 "
        "{%0,%1,%2,%3}, {%4,%5,%6,%7}, {%8,%9}, {%0,%1,%2,%3};\n"
        : "+f"(c[0]), "+f"(c[1]), "+f"(c[2]), "+f"(c[3])
        : "r"(a[0]), "r"(a[1]), "r"(a[2]), "r"(a[3]), "r"(b[0]), "r"(b[1]));
}

__device__ __forceinline__ void cpasync16(float* dst_smem, const float* src) {
    uint32_t d = (uint32_t)__cvta_generic_to_shared(dst_smem);
    asm volatile("cp.async.cg.shared.global [%0], [%1], 16;" :: "r"(d), "l"(src));
}
__device__ __forceinline__ void cp_commit() { asm volatile("cp.async.commit_group;"); }
template <int N>
__device__ __forceinline__ void cp_wait() { asm volatile("cp.async.wait_group %0;" :: "n"(N)); }

// ---------------------------------------------------------------------------
// Router: gate logits, top-2, softmax -> dense weight vector w[4]
// ---------------------------------------------------------------------------
__global__ __launch_bounds__(256) void router_kernel(const float* __restrict__ x,
                                                     const float* __restrict__ Wgate) {
    int gtid  = blockIdx.x * 256 + threadIdx.x;
    int token = gtid >> 5;
    int lane  = gtid & 31;
    const float* xr = x + (size_t)token * D_MODEL;

    float a0 = 0.f, a1 = 0.f, a2 = 0.f, a3 = 0.f;
    #pragma unroll 8
    for (int k = lane; k < D_MODEL; k += 32) {
        float xv = xr[k];
        a0 = fmaf(xv, Wgate[k],               a0);
        a1 = fmaf(xv, Wgate[D_MODEL + k],     a1);
        a2 = fmaf(xv, Wgate[2 * D_MODEL + k], a2);
        a3 = fmaf(xv, Wgate[3 * D_MODEL + k], a3);
    }
    #pragma unroll
    for (int o = 16; o; o >>= 1) {
        a0 += __shfl_down_sync(0xffffffffu, a0, o);
        a1 += __shfl_down_sync(0xffffffffu, a1, o);
        a2 += __shfl_down_sync(0xffffffffu, a2, o);
        a3 += __shfl_down_sync(0xffffffffu, a3, o);
    }
    if (lane == 0) {
        float l[4] = {a0, a1, a2, a3};
        int i0 = 0;
        #pragma unroll
        for (int i = 1; i < 4; i++) if (l[i] > l[i0]) i0 = i;
        int i1 = -1;
        #pragma unroll
        for (int i = 0; i < 4; i++) if (i != i0 && (i1 < 0 || l[i] > l[i1])) i1 = i;
        float ex = __expf(l[i1] - l[i0]);
        float den = 1.0f + ex;
        float wv[4] = {0.f, 0.f, 0.f, 0.f};
        wv[i0] = 1.0f / den;
        wv[i1] = ex / den;
        *(float4*)(g_w + (size_t)token * NEXP) = make_float4(wv[0], wv[1], wv[2], wv[3]);
    }
}

// ---------------------------------------------------------------------------
// Fused projection GEMM (tf32 mma.sync, 2-stage cp.async pipeline)
// CTA tile 128(M) x 32(N), 3 matrices (g,v,d) fused. 8 warps: 4(M) x 2(N),
// warp tile 32x16. Epilogue applies activations, writes x_scan + a.
// ---------------------------------------------------------------------------
__global__ __launch_bounds__(256, 2) void proj_gemm_kernel(
    const float* __restrict__ x,
    const float* __restrict__ Wg, const float* __restrict__ bg,
    const float* __restrict__ Wv, const float* __restrict__ bv,
    const float* __restrict__ Wd, const float* __restrict__ bd)
{
    extern __shared__ float smem[];

    const int e     = blockIdx.z;
    const int mBase = blockIdx.y * BM;
    const int nBase = blockIdx.x * BN;

    const float* Wmat[3] = {
        Wg + (size_t)e * D_MODEL * D_MODEL,
        Wv + (size_t)e * D_MODEL * D_MODEL,
        Wd + (size_t)e * D_MODEL * D_MODEL };

    const int tid  = threadIdx.x;
    const int wid  = tid >> 5, lane = tid & 31;
    const int wm   = wid >> 1, wn = wid & 1;       // warp grid 4(M) x 2(N)
    const int grp  = lane >> 2, qid = lane & 3;

    // Precompute cp.async source/dest coordinates
    // A: 4 chunks of 256 float4s; B: 3 chunks
    const int a_row = tid >> 3;            // 0..31 (+32*r)
    const int a_c4  = (tid & 7) * 4;

    float acc[3][2][2][4];
    #pragma unroll
    for (int m = 0; m < 3; m++)
        #pragma unroll
        for (int i = 0; i < 2; i++)
            #pragma unroll
            for (int j = 0; j < 2; j++)
                #pragma unroll
                for (int r = 0; r < 4; r++) acc[m][i][j][r] = 0.f;

    auto load_stage = [&](int kb, int st) {
        float* sA = smem + st * STAGE_FLOATS;
        float* sB = sA + A_STAGE;
        const int kcol = kb * BK;
        #pragma unroll
        for (int r = 0; r < 4; r++) {
            int row = a_row + r * 32;
            cpasync16(sA + row * AW + a_c4,
                      x + (size_t)(mBase + row) * D_MODEL + kcol + a_c4);
        }
        #pragma unroll
        for (int r = 0; r < 3; r++) {
            int idx = tid + r * 256;          // 0..767
            int mat = idx >> 8;
            int row = (idx >> 3) & 31;
            int c4  = (idx & 7) * 4;
            cpasync16(sB + mat * (BN * AW) + row * AW + c4,
                      Wmat[mat] + (size_t)(nBase + row) * D_MODEL + kcol + c4);
        }
    };

    load_stage(0, 0);
    cp_commit();

    const int NKB = D_MODEL / BK;          // 32
    for (int kb = 0; kb < NKB; kb++) {
        if (kb + 1 < NKB) {
            load_stage(kb + 1, (kb + 1) & 1);
            cp_commit();
            cp_wait<1>();
        } else {
            cp_wait<0>();
        }
        __syncthreads();

        const float* sA = smem + (kb & 1) * STAGE_FLOATS;
        const float* sB = sA + A_STAGE;

        #pragma unroll
        for (int k8 = 0; k8 < BK; k8 += 8) {
            uint32_t af[2][4];
            #pragma unroll
            for (int i = 0; i < 2; i++) {
                int r0 = wm * 32 + i * 16 + grp;
                af[i][0] = f2tf32(sA[r0 * AW + k8 + qid]);
                af[i][1] = f2tf32(sA[(r0 + 8) * AW + k8 + qid]);
                af[i][2] = f2tf32(sA[r0 * AW + k8 + qid + 4]);
                af[i][3] = f2tf32(sA[(r0 + 8) * AW + k8 + qid + 4]);
            }
            #pragma unroll
            for (int m = 0; m < 3; m++) {
                const float* sBm = sB + m * (BN * AW);
                #pragma unroll
                for (int j = 0; j < 2; j++) {
                    int n0 = wn * 16 + j * 8 + grp;
                    uint32_t bf[2];
                    bf[0] = f2tf32(sBm[n0 * AW + k8 + qid]);
                    bf[1] = f2tf32(sBm[n0 * AW + k8 + qid + 4]);
                    #pragma unroll
                    for (int i = 0; i < 2; i++)
                        mma_tf32(acc[m][i][j], af[i], bf);
                }
            }
        }
        __syncthreads();
    }

    // ---- fused epilogue: bias + activations -> g_xs / g_a ----
    const float* bias0 = bg + e * D_MODEL;
    const float* bias1 = bv + e * D_MODEL;
    const float* bias2 = bd + e * D_MODEL;
    #pragma unroll
    for (int i = 0; i < 2; i++)
        #pragma unroll
        for (int j = 0; j < 2; j++)
            #pragma unroll
            for (int h = 0; h < 2; h++) {
                int row = mBase + wm * 32 + i * 16 + grp + h * 8;
                int col = nBase + wn * 16 + j * 8 + qid * 2;
                float g0 = acc[0][i][j][h * 2 + 0] + bias0[col];
                float g1 = acc[0][i][j][h * 2 + 1] + bias0[col + 1];
                float v0 = acc[1][i][j][h * 2 + 0] + bias1[col];
                float v1 = acc[1][i][j][h * 2 + 1] + bias1[col + 1];
                float d0 = acc[2][i][j][h * 2 + 0] + bias2[col];
                float d1 = acc[2][i][j][h * 2 + 1] + bias2[col + 1];
                float2 xs = make_float2(sigmoid_acc(g0) * tanh_acc(v0),
                                        sigmoid_acc(g1) * tanh_acc(v1));
                float2 av = make_float2(0.001f + 0.998f * sigmoid_acc(d0),
                                        0.001f + 0.998f * sigmoid_acc(d1));
                size_t base = ((size_t)e * NTOK + row) * D_MODEL + col;
                *(float2*)(g_xs + base) = xs;
                *(float2*)(g_a  + base) = av;
            }
}

// ---------------------------------------------------------------------------
// Chunked linear scan: h_t = a_t*h_{t-1} + x_t
// ---------------------------------------------------------------------------
__global__ __launch_bounds__(256) void scan_pass1() {
    int d  = blockIdx.x * 256 + threadIdx.x;
    int c  = blockIdx.y;
    int eb = blockIdx.z;
    size_t base = ((size_t)eb * S_LEN + c * CHUNK) * D_MODEL + d;
    float A = 1.f, X = 0.f;
    #pragma unroll 8
    for (int t = 0; t < CHUNK; t++) {
        float a  = g_a [base + (size_t)t * D_MODEL];
        float xv = g_xs[base + (size_t)t * D_MODEL];
        X = fmaf(a, X, xv);
        A *= a;
    }
    int sidx = (eb * NCHUNK + c) * D_MODEL + d;
    g_sumA[sidx] = A;
    g_sumX[sidx] = X;
}

__global__ __launch_bounds__(256) void scan_pass2() {
    int idx = blockIdx.x * 256 + threadIdx.x;
    int eb = idx >> 10, d = idx & 1023;
    float h = 0.f;
    for (int c = 0; c < NCHUNK; c++) {
        int s = (eb * NCHUNK + c) * D_MODEL + d;
        g_hstart[s] = h;
        h = fmaf(g_sumA[s], h, g_sumX[s]);
    }
}

__global__ __launch_bounds__(256) void scan_pass3(float* __restrict__ out) {
    int d = blockIdx.x * 256 + threadIdx.x;
    int c = blockIdx.y;
    int b = blockIdx.z;
    __shared__ float ws[CHUNK * NEXP];
    int t0 = c * CHUNK;
    ws[threadIdx.x] = g_w[(size_t)(b * S_LEN + t0) * NEXP + threadIdx.x];
    __syncthreads();

    float  h[NEXP];
    size_t xbase[NEXP];
    #pragma unroll
    for (int e = 0; e < NEXP; e++) {
        int eb = e * BATCH + b;
        h[e]     = g_hstart[(eb * NCHUNK + c) * D_MODEL + d];
        xbase[e] = ((size_t)eb * S_LEN + t0) * D_MODEL + d;
    }
    float* op = out + ((size_t)(b * S_LEN + t0)) * D_MODEL + d;
    #pragma unroll 4
    for (int t = 0; t < CHUNK; t++) {
        float acc = 0.f;
        #pragma unroll
        for (int e = 0; e < NEXP; e++) {
            size_t idx = xbase[e] + (size_t)t * D_MODEL;
            h[e] = fmaf(g_a[idx], h[e], g_xs[idx]);
            acc  = fmaf(ws[t * NEXP + e], h[e], acc);
        }
        op[(size_t)t * D_MODEL] = acc;
    }
}

// ---------------------------------------------------------------------------
// Launch
// ---------------------------------------------------------------------------
extern "C" void kernel_launch(void* const* d_in, const int* in_sizes, int n_in,
                              void* d_out, int out_size) {
    const float* x     = (const float*)d_in[0];
    const float* Wg    = (const float*)d_in[1];
    const float* bg    = (const float*)d_in[2];
    const float* Wv    = (const float*)d_in[3];
    const float* bv    = (const float*)d_in[4];
    const float* Wd    = (const float*)d_in[5];
    const float* bd    = (const float*)d_in[6];
    const float* Wgate = (const float*)d_in[7];
    float* out = (float*)d_out;

    cudaFuncSetAttribute(proj_gemm_kernel,
                         cudaFuncAttributeMaxDynamicSharedMemorySize, SMEM_BYTES);

    router_kernel<<<(NTOK * 32) / 256, 256>>>(x, Wgate);
    proj_gemm_kernel<<<dim3(D_MODEL / BN, NTOK / BM, NEXP), 256, SMEM_BYTES>>>(
        x, Wg, bg, Wv, bv, Wd, bd);
    scan_pass1<<<dim3(D_MODEL / 256, NCHUNK, NEXP * BATCH), 256>>>();
    scan_pass2<<<(NEXP * BATCH * D_MODEL) / 256, 256>>>();
    scan_pass3<<<dim3(D_MODEL / 256, NCHUNK, BATCH), 256>>>(out);
}

// round 4
// speedup vs baseline: 2.3569x; 1.1092x over previous
#include <cuda_runtime.h>
#include <cstdint>
#include <math.h>

// ---------------------------------------------------------------------------
// Problem constants
// ---------------------------------------------------------------------------
#define D_MODEL 1024
#define S_LEN   4096
#define BATCH   4
#define NEXP    4
#define NTOK    16384
#define CHUNK   64
#define NCHUNK  64

// GEMM tiling
#define BM 128
#define BN 64
#define BK 32
#define NKB (D_MODEL / BK)          // 32
#define PITCH 144                   // bytes per smem row (32 floats + 16B pad)
#define AROWS BM                    // 128
#define BROWS (3 * BN)              // 192
#define STG_ROWS (AROWS + BROWS)    // 320
#define STG_BYTES (STG_ROWS * PITCH)        // 46080
#define SMEM_BYTES (2 * STG_BYTES)          // 92160

// ---------------------------------------------------------------------------
// Scratch (device globals; no dynamic allocation allowed)
// ---------------------------------------------------------------------------
__device__ float g_xs[(size_t)NEXP * NTOK * D_MODEL];
__device__ float g_a [(size_t)NEXP * NTOK * D_MODEL];
__device__ float g_sumA  [NEXP * BATCH * NCHUNK * D_MODEL];
__device__ float g_sumX  [NEXP * BATCH * NCHUNK * D_MODEL];
__device__ float g_hstart[NEXP * BATCH * NCHUNK * D_MODEL];
__device__ float g_w[NTOK * NEXP];
__device__ float g_xr[(size_t)NTOK * D_MODEL];                 // tf32-rounded x
__device__ float g_wr[(size_t)3 * NEXP * D_MODEL * D_MODEL];   // tf32-rounded W

// ---------------------------------------------------------------------------
// Helpers
// ---------------------------------------------------------------------------
__device__ __forceinline__ float tf32r(float x) {
    uint32_t u; asm("cvt.rna.tf32.f32 %0, %1;" : "=r"(u) : "f"(x));
    return __uint_as_float(u);
}
__device__ __forceinline__ float ex2f_(float x) {
    float y; asm("ex2.approx.f32 %0, %1;" : "=f"(y) : "f"(x)); return y;
}
__device__ __forceinline__ float frcp_(float x) {
    float y = __uint_as_float(0x7EF311C3u - __float_as_uint(x));
    y = y * (2.0f - x * y);
    y = y * (2.0f - x * y);
    y = y * (2.0f - x * y);
    return y;
}
__device__ __forceinline__ float sigmoid_acc(float z) {
    z = fminf(fmaxf(z, -30.0f), 30.0f);
    return frcp_(1.0f + ex2f_(-1.4426950408889634f * z));
}
__device__ __forceinline__ float tanh_acc(float v) {
    v = fminf(fmaxf(v, -9.0f), 9.0f);
    float t = ex2f_(2.8853900817779268f * v);
    return (t - 1.0f) * frcp_(t + 1.0f);
}

__device__ __forceinline__ void mma_tf32(float* c, const uint32_t* a, const uint32_t* b) {
    asm volatile(
        "mma.sync.aligned.m16n8k8.row.col.f32.tf32.tf32.f32 "
        "{%0,%1,%2,%3}, {%4,%5,%6,%7}, {%8,%9}, {%0,%1,%2,%3};\n"
        : "+f"(c[0]), "+f"(c[1]), "+f"(c[2]), "+f"(c[3])
        : "r"(a[0]), "r"(a[1]), "r"(a[2]), "r"(a[3]), "r"(b[0]), "r"(b[1]));
}

__device__ __forceinline__ void ldsm4(uint32_t* r, uint32_t addr) {
    asm volatile(
        "ldmatrix.sync.aligned.m8n8.x4.shared.b16 {%0,%1,%2,%3}, [%4];"
        : "=r"(r[0]), "=r"(r[1]), "=r"(r[2]), "=r"(r[3]) : "r"(addr));
}

__device__ __forceinline__ void cpasync16(uint32_t dst_smem, const float* src) {
    asm volatile("cp.async.cg.shared.global [%0], [%1], 16;" :: "r"(dst_smem), "l"(src));
}
__device__ __forceinline__ void cp_commit() { asm volatile("cp.async.commit_group;"); }
template <int N>
__device__ __forceinline__ void cp_wait() { asm volatile("cp.async.wait_group %0;" :: "n"(N)); }

// ---------------------------------------------------------------------------
// Pre-pass: round fp32 -> tf32 (rna)
// ---------------------------------------------------------------------------
__global__ __launch_bounds__(256) void round_tf32_kernel(const float4* __restrict__ src,
                                                         float4* __restrict__ dst) {
    int i = blockIdx.x * 256 + threadIdx.x;
    float4 v = src[i];
    v.x = tf32r(v.x); v.y = tf32r(v.y); v.z = tf32r(v.z); v.w = tf32r(v.w);
    dst[i] = v;
}

// ---------------------------------------------------------------------------
// Router
// ---------------------------------------------------------------------------
__global__ __launch_bounds__(256) void router_kernel(const float* __restrict__ x,
                                                     const float* __restrict__ Wgate) {
    int gtid  = blockIdx.x * 256 + threadIdx.x;
    int token = gtid >> 5;
    int lane  = gtid & 31;
    const float* xr = x + (size_t)token * D_MODEL;

    float a0 = 0.f, a1 = 0.f, a2 = 0.f, a3 = 0.f;
    #pragma unroll 8
    for (int k = lane; k < D_MODEL; k += 32) {
        float xv = xr[k];
        a0 = fmaf(xv, Wgate[k],               a0);
        a1 = fmaf(xv, Wgate[D_MODEL + k],     a1);
        a2 = fmaf(xv, Wgate[2 * D_MODEL + k], a2);
        a3 = fmaf(xv, Wgate[3 * D_MODEL + k], a3);
    }
    #pragma unroll
    for (int o = 16; o; o >>= 1) {
        a0 += __shfl_down_sync(0xffffffffu, a0, o);
        a1 += __shfl_down_sync(0xffffffffu, a1, o);
        a2 += __shfl_down_sync(0xffffffffu, a2, o);
        a3 += __shfl_down_sync(0xffffffffu, a3, o);
    }
    if (lane == 0) {
        float l[4] = {a0, a1, a2, a3};
        int i0 = 0;
        #pragma unroll
        for (int i = 1; i < 4; i++) if (l[i] > l[i0]) i0 = i;
        int i1 = -1;
        #pragma unroll
        for (int i = 0; i < 4; i++) if (i != i0 && (i1 < 0 || l[i] > l[i1])) i1 = i;
        float ex = __expf(l[i1] - l[i0]);
        float den = 1.0f + ex;
        float wv[4] = {0.f, 0.f, 0.f, 0.f};
        wv[i0] = 1.0f / den;
        wv[i1] = ex / den;
        *(float4*)(g_w + (size_t)token * NEXP) = make_float4(wv[0], wv[1], wv[2], wv[3]);
    }
}

// ---------------------------------------------------------------------------
// Fused projection GEMM: tf32 mma.sync + ldmatrix, 2-stage cp.async pipeline.
// CTA 128(M) x 64(N) x 3 matrices. 8 warps = 2(M) x 4(N), warp tile 64x16.
// ---------------------------------------------------------------------------
__global__ __launch_bounds__(256, 2) void proj_gemm_kernel(
    const float* __restrict__ bg, const float* __restrict__ bv,
    const float* __restrict__ bd)
{
    extern __shared__ char smem[];
    const uint32_t sbase = (uint32_t)__cvta_generic_to_shared(smem);

    const int e     = blockIdx.z;
    const int mBase = blockIdx.x * BM;
    const int nBase = blockIdx.y * BN;

    const int tid  = threadIdx.x;
    const int wid  = tid >> 5, lane = tid & 31;
    const int wm   = wid >> 2, wn = wid & 3;   // 2(M) x 4(N)
    const int grp  = lane >> 2, qid = lane & 3;

    const float* xr = g_xr;
    const float* wmat[3] = {
        g_wr + (size_t)0 * NEXP * D_MODEL * D_MODEL + (size_t)e * D_MODEL * D_MODEL,
        g_wr + (size_t)1 * NEXP * D_MODEL * D_MODEL + (size_t)e * D_MODEL * D_MODEL,
        g_wr + (size_t)2 * NEXP * D_MODEL * D_MODEL + (size_t)e * D_MODEL * D_MODEL };

    // ldmatrix per-lane address components
    // A (per i): lanes 0-7: rows r0+l, k+0 | 8-15: rows r0+8+(l-8), k+0
    //            16-23: rows r0+(l-16), k+16B | 24-31: rows r0+8+(l-24), k+16B
    const int rA  = wm * 64 + ((lane >> 3) & 1) * 8 + (lane & 7);
    const int kA  = (lane >> 4) * 16;
    // B (per mat): lanes 0-7: rows n0+l, k+0 | 8-15: rows n0+(l-8), k+16B
    //              16-23: rows n0+8+(l-16), k+0 | 24-31: rows n0+8+(l-24), k+16B
    const int rB  = wn * 16 + ((lane >> 4) & 1) * 8 + (lane & 7);
    const int kB  = ((lane >> 3) & 1) * 16;

    const uint32_t addrA0 = sbase + (uint32_t)rA * PITCH + kA;
    const uint32_t addrB0 = sbase + (uint32_t)(AROWS + rB) * PITCH + kB;

    float acc[3][4][2][4];
    #pragma unroll
    for (int m = 0; m < 3; m++)
        #pragma unroll
        for (int i = 0; i < 4; i++)
            #pragma unroll
            for (int j = 0; j < 2; j++)
                #pragma unroll
                for (int r = 0; r < 4; r++) acc[m][i][j][r] = 0.f;

    // producer: 2560 16B-chunks per stage, 10 per thread
    auto load_stage = [&](int kb, int st) {
        const uint32_t dst0 = sbase + st * STG_BYTES;
        const int kcol = kb * BK;
        #pragma unroll
        for (int it = 0; it < 10; it++) {
            int cid = tid + it * 256;
            int row = cid >> 3, c = cid & 7;
            const float* src;
            if (row < AROWS) {
                src = xr + (size_t)(mBase + row) * D_MODEL + kcol + c * 4;
            } else {
                int r2 = row - AROWS;
                src = wmat[r2 >> 6] + (size_t)(nBase + (r2 & 63)) * D_MODEL + kcol + c * 4;
            }
            cpasync16(dst0 + (uint32_t)row * PITCH + c * 16, src);
        }
    };

    load_stage(0, 0);
    cp_commit();

    for (int kb = 0; kb < NKB; kb++) {
        if (kb + 1 < NKB) {
            load_stage(kb + 1, (kb + 1) & 1);
            cp_commit();
            cp_wait<1>();
        } else {
            cp_wait<0>();
        }
        __syncthreads();

        const uint32_t stoff = (kb & 1) * STG_BYTES;
        const uint32_t aA = addrA0 + stoff;
        const uint32_t aB = addrB0 + stoff;

        #pragma unroll
        for (int k8 = 0; k8 < 4; k8++) {
            uint32_t af[4][4];
            #pragma unroll
            for (int i = 0; i < 4; i++)
                ldsm4(af[i], aA + i * (16 * PITCH) + k8 * 32);
            #pragma unroll
            for (int m = 0; m < 3; m++) {
                uint32_t bf[4];
                ldsm4(bf, aB + m * (64 * PITCH) + k8 * 32);
                #pragma unroll
                for (int j = 0; j < 2; j++)
                    #pragma unroll
                    for (int i = 0; i < 4; i++)
                        mma_tf32(acc[m][i][j], af[i], bf + 2 * j);
            }
        }
        __syncthreads();
    }

    // ---- fused epilogue ----
    const float* bias0 = bg + e * D_MODEL;
    const float* bias1 = bv + e * D_MODEL;
    const float* bias2 = bd + e * D_MODEL;
    #pragma unroll
    for (int i = 0; i < 4; i++)
        #pragma unroll
        for (int j = 0; j < 2; j++)
            #pragma unroll
            for (int h = 0; h < 2; h++) {
                int row = mBase + wm * 64 + i * 16 + grp + h * 8;
                int col = nBase + wn * 16 + j * 8 + qid * 2;
                float g0 = acc[0][i][j][h * 2 + 0] + __ldg(bias0 + col);
                float g1 = acc[0][i][j][h * 2 + 1] + __ldg(bias0 + col + 1);
                float v0 = acc[1][i][j][h * 2 + 0] + __ldg(bias1 + col);
                float v1 = acc[1][i][j][h * 2 + 1] + __ldg(bias1 + col + 1);
                float d0 = acc[2][i][j][h * 2 + 0] + __ldg(bias2 + col);
                float d1 = acc[2][i][j][h * 2 + 1] + __ldg(bias2 + col + 1);
                float2 xs = make_float2(sigmoid_acc(g0) * tanh_acc(v0),
                                        sigmoid_acc(g1) * tanh_acc(v1));
                float2 av = make_float2(0.001f + 0.998f * sigmoid_acc(d0),
                                        0.001f + 0.998f * sigmoid_acc(d1));
                size_t base = ((size_t)e * NTOK + row) * D_MODEL + col;
                *(float2*)(g_xs + base) = xs;
                *(float2*)(g_a  + base) = av;
            }
}

// ---------------------------------------------------------------------------
// Chunked linear scan
// ---------------------------------------------------------------------------
__global__ __launch_bounds__(256) void scan_pass1() {
    int d  = blockIdx.x * 256 + threadIdx.x;
    int c  = blockIdx.y;
    int eb = blockIdx.z;
    size_t base = ((size_t)eb * S_LEN + c * CHUNK) * D_MODEL + d;
    float A = 1.f, X = 0.f;
    #pragma unroll 8
    for (int t = 0; t < CHUNK; t++) {
        float a  = g_a [base + (size_t)t * D_MODEL];
        float xv = g_xs[base + (size_t)t * D_MODEL];
        X = fmaf(a, X, xv);
        A *= a;
    }
    int sidx = (eb * NCHUNK + c) * D_MODEL + d;
    g_sumA[sidx] = A;
    g_sumX[sidx] = X;
}

__global__ __launch_bounds__(256) void scan_pass2() {
    int idx = blockIdx.x * 256 + threadIdx.x;
    int eb = idx >> 10, d = idx & 1023;
    float h = 0.f;
    for (int c = 0; c < NCHUNK; c++) {
        int s = (eb * NCHUNK + c) * D_MODEL + d;
        g_hstart[s] = h;
        h = fmaf(g_sumA[s], h, g_sumX[s]);
    }
}

__global__ __launch_bounds__(256) void scan_pass3(float* __restrict__ out) {
    int d = blockIdx.x * 256 + threadIdx.x;
    int c = blockIdx.y;
    int b = blockIdx.z;
    __shared__ float ws[CHUNK * NEXP];
    int t0 = c * CHUNK;
    ws[threadIdx.x] = g_w[(size_t)(b * S_LEN + t0) * NEXP + threadIdx.x];
    __syncthreads();

    float  h[NEXP];
    size_t xbase[NEXP];
    #pragma unroll
    for (int e = 0; e < NEXP; e++) {
        int eb = e * BATCH + b;
        h[e]     = g_hstart[(eb * NCHUNK + c) * D_MODEL + d];
        xbase[e] = ((size_t)eb * S_LEN + t0) * D_MODEL + d;
    }
    float* op = out + ((size_t)(b * S_LEN + t0)) * D_MODEL + d;
    #pragma unroll 4
    for (int t = 0; t < CHUNK; t++) {
        float acc = 0.f;
        #pragma unroll
        for (int e = 0; e < NEXP; e++) {
            size_t idx = xbase[e] + (size_t)t * D_MODEL;
            h[e] = fmaf(g_a[idx], h[e], g_xs[idx]);
            acc  = fmaf(ws[t * NEXP + e], h[e], acc);
        }
        op[(size_t)t * D_MODEL] = acc;
    }
}

// ---------------------------------------------------------------------------
// Launch
// ---------------------------------------------------------------------------
extern "C" void kernel_launch(void* const* d_in, const int* in_sizes, int n_in,
                              void* d_out, int out_size) {
    const float* x     = (const float*)d_in[0];
    const float* Wg    = (const float*)d_in[1];
    const float* bg    = (const float*)d_in[2];
    const float* Wv    = (const float*)d_in[3];
    const float* bv    = (const float*)d_in[4];
    const float* Wd    = (const float*)d_in[5];
    const float* bd    = (const float*)d_in[6];
    const float* Wgate = (const float*)d_in[7];
    float* out = (float*)d_out;

    cudaFuncSetAttribute(proj_gemm_kernel,
                         cudaFuncAttributeMaxDynamicSharedMemorySize, SMEM_BYTES);

    float* xr_p; cudaGetSymbolAddress((void**)&xr_p, g_xr);
    float* wr_p; cudaGetSymbolAddress((void**)&wr_p, g_wr);
    const size_t WSTRIDE = (size_t)NEXP * D_MODEL * D_MODEL;

    round_tf32_kernel<<<(NTOK * D_MODEL / 4) / 256, 256>>>((const float4*)x, (float4*)xr_p);
    round_tf32_kernel<<<(int)(WSTRIDE / 4) / 256, 256>>>((const float4*)Wg, (float4*)(wr_p + 0 * WSTRIDE));
    round_tf32_kernel<<<(int)(WSTRIDE / 4) / 256, 256>>>((const float4*)Wv, (float4*)(wr_p + 1 * WSTRIDE));
    round_tf32_kernel<<<(int)(WSTRIDE / 4) / 256, 256>>>((const float4*)Wd, (float4*)(wr_p + 2 * WSTRIDE));

    router_kernel<<<(NTOK * 32) / 256, 256>>>(x, Wgate);

    proj_gemm_kernel<<<dim3(NTOK / BM, D_MODEL / BN, NEXP), 256, SMEM_BYTES>>>(bg, bv, bd);

    scan_pass1<<<dim3(D_MODEL / 256, NCHUNK, NEXP * BATCH), 256>>>();
    scan_pass2<<<(NEXP * BATCH * D_MODEL) / 256, 256>>>();
    scan_pass3<<<dim3(D_MODEL / 256, NCHUNK, BATCH), 256>>>(out);
}

// round 5
// speedup vs baseline: 3.9844x; 1.6905x over previous
#include <cuda_runtime.h>
#include <cuda_fp16.h>
#include <cstdint>
#include <math.h>

// ---------------------------------------------------------------------------
// Problem constants
// ---------------------------------------------------------------------------
#define D_MODEL 1024
#define S_LEN   4096
#define BATCH   4
#define NEXP    4
#define NTOK    16384
#define CHUNK   64
#define NCHUNK  64

// GEMM tiling (fp16 mma.m16n8k16)
#define BM 128
#define BN 64
#define BKH 64                      // K halves per stage (=128 bytes/row)
#define NKB (D_MODEL / BKH)         // 16 stages
#define PITCH 144                   // bytes per smem row (128B data + 16B pad)
#define AROWS BM                    // 128
#define BROWS (3 * BN)              // 192
#define STG_ROWS (AROWS + BROWS)    // 320
#define STG_BYTES (STG_ROWS * PITCH)        // 46080
#define SMEM_BYTES (2 * STG_BYTES)          // 92160

// ---------------------------------------------------------------------------
// Scratch (device globals; no dynamic allocation allowed)
// ---------------------------------------------------------------------------
__device__ float g_xs[(size_t)NEXP * NTOK * D_MODEL];
__device__ float g_a [(size_t)NEXP * NTOK * D_MODEL];
__device__ float g_sumA  [NEXP * BATCH * NCHUNK * D_MODEL];
__device__ float g_sumX  [NEXP * BATCH * NCHUNK * D_MODEL];
__device__ float g_hstart[NEXP * BATCH * NCHUNK * D_MODEL];
__device__ float g_w[NTOK * NEXP];
__device__ __half g_xh[(size_t)NTOK * D_MODEL];                  // fp16 x
__device__ __half g_wh[(size_t)3 * NEXP * D_MODEL * D_MODEL];    // fp16 W (mat-major)

// ---------------------------------------------------------------------------
// Helpers
// ---------------------------------------------------------------------------
// exp2 on FMA/ALU pipes only (no MUFU): |t| <= ~60, rel err ~1e-6
__device__ __forceinline__ float exp2_fma(float t) {
    float r  = t + 12582912.0f;              // round-to-int in mantissa (2^23*1.5)
    int   ir = __float_as_int(r);
    float f  = t - (r - 12582912.0f);        // f in [-0.5, 0.5]
    float p  = 1.3333558146e-3f;
    p = fmaf(p, f, 9.6180886130e-3f);
    p = fmaf(p, f, 5.5504108664e-2f);
    p = fmaf(p, f, 2.4022650696e-1f);
    p = fmaf(p, f, 6.9314718056e-1f);
    p = fmaf(p, f, 1.0f);
    float s = __int_as_float((ir << 23) + 0x3F800000);
    return s * p;
}
// FMA-pipe reciprocal (x > 0): bit-trick seed + 3 Newton steps
__device__ __forceinline__ float frcp_(float x) {
    float y = __uint_as_float(0x7EF311C3u - __float_as_uint(x));
    y = y * (2.0f - x * y);
    y = y * (2.0f - x * y);
    y = y * (2.0f - x * y);
    return y;
}
__device__ __forceinline__ float sigmoid_acc(float z) {
    z = fminf(fmaxf(z, -30.0f), 30.0f);
    return frcp_(1.0f + exp2_fma(-1.4426950408889634f * z));
}
__device__ __forceinline__ float tanh_acc(float v) {
    v = fminf(fmaxf(v, -9.0f), 9.0f);
    float t = exp2_fma(2.8853900817779268f * v);   // e^{2v}
    return (t - 1.0f) * frcp_(t + 1.0f);
}

__device__ __forceinline__ void mma_f16(float* c, const uint32_t* a, const uint32_t* b) {
    asm volatile(
        "mma.sync.aligned.m16n8k16.row.col.f32.f16.f16.f32 "
        "{%0,%1,%2,%3}, {%4,%5,%6,%7}, {%8,%9}, {%0,%1,%2,%3};\n"
        : "+f"(c[0]), "+f"(c[1]), "+f"(c[2]), "+f"(c[3])
        : "r"(a[0]), "r"(a[1]), "r"(a[2]), "r"(a[3]), "r"(b[0]), "r"(b[1]));
}

__device__ __forceinline__ void ldsm4(uint32_t* r, uint32_t addr) {
    asm volatile(
        "ldmatrix.sync.aligned.m8n8.x4.shared.b16 {%0,%1,%2,%3}, [%4];"
        : "=r"(r[0]), "=r"(r[1]), "=r"(r[2]), "=r"(r[3]) : "r"(addr));
}

__device__ __forceinline__ void cpasync16(uint32_t dst_smem, const void* src) {
    asm volatile("cp.async.cg.shared.global [%0], [%1], 16;" :: "r"(dst_smem), "l"(src));
}
__device__ __forceinline__ void cp_commit() { asm volatile("cp.async.commit_group;"); }
template <int N>
__device__ __forceinline__ void cp_wait() { asm volatile("cp.async.wait_group %0;" :: "n"(N)); }

// ---------------------------------------------------------------------------
// Pre-pass: fp32 -> fp16 (rn)
// ---------------------------------------------------------------------------
__global__ __launch_bounds__(256) void f2h_kernel(const float4* __restrict__ src,
                                                  __half2* __restrict__ dst) {
    int i = blockIdx.x * 256 + threadIdx.x;
    float4 v = src[i];
    dst[2 * i]     = __floats2half2_rn(v.x, v.y);
    dst[2 * i + 1] = __floats2half2_rn(v.z, v.w);
}

// ---------------------------------------------------------------------------
// Router
// ---------------------------------------------------------------------------
__global__ __launch_bounds__(256) void router_kernel(const float* __restrict__ x,
                                                     const float* __restrict__ Wgate) {
    int gtid  = blockIdx.x * 256 + threadIdx.x;
    int token = gtid >> 5;
    int lane  = gtid & 31;
    const float* xr = x + (size_t)token * D_MODEL;

    float a0 = 0.f, a1 = 0.f, a2 = 0.f, a3 = 0.f;
    #pragma unroll 8
    for (int k = lane; k < D_MODEL; k += 32) {
        float xv = xr[k];
        a0 = fmaf(xv, Wgate[k],               a0);
        a1 = fmaf(xv, Wgate[D_MODEL + k],     a1);
        a2 = fmaf(xv, Wgate[2 * D_MODEL + k], a2);
        a3 = fmaf(xv, Wgate[3 * D_MODEL + k], a3);
    }
    #pragma unroll
    for (int o = 16; o; o >>= 1) {
        a0 += __shfl_down_sync(0xffffffffu, a0, o);
        a1 += __shfl_down_sync(0xffffffffu, a1, o);
        a2 += __shfl_down_sync(0xffffffffu, a2, o);
        a3 += __shfl_down_sync(0xffffffffu, a3, o);
    }
    if (lane == 0) {
        float l[4] = {a0, a1, a2, a3};
        int i0 = 0;
        #pragma unroll
        for (int i = 1; i < 4; i++) if (l[i] > l[i0]) i0 = i;
        int i1 = -1;
        #pragma unroll
        for (int i = 0; i < 4; i++) if (i != i0 && (i1 < 0 || l[i] > l[i1])) i1 = i;
        float ex = __expf(l[i1] - l[i0]);
        float den = 1.0f + ex;
        float wv[4] = {0.f, 0.f, 0.f, 0.f};
        wv[i0] = 1.0f / den;
        wv[i1] = ex / den;
        *(float4*)(g_w + (size_t)token * NEXP) = make_float4(wv[0], wv[1], wv[2], wv[3]);
    }
}

// ---------------------------------------------------------------------------
// Fused projection GEMM: fp16 mma.m16n8k16 + ldmatrix, 2-stage cp.async.
// CTA 128(M) x 64(N) x 3 matrices. 8 warps = 2(M) x 4(N), warp tile 64x16.
// Stage covers K=64 halves (128B rows). Epilogue: FMA-pipe activations.
// ---------------------------------------------------------------------------
__global__ __launch_bounds__(256, 2) void proj_gemm_kernel(
    const float* __restrict__ bg, const float* __restrict__ bv,
    const float* __restrict__ bd)
{
    extern __shared__ char smem[];
    const uint32_t sbase = (uint32_t)__cvta_generic_to_shared(smem);

    const int e     = blockIdx.z;
    const int mBase = blockIdx.x * BM;
    const int nBase = blockIdx.y * BN;

    const int tid  = threadIdx.x;
    const int wid  = tid >> 5, lane = tid & 31;
    const int wm   = wid >> 2, wn = wid & 3;   // 2(M) x 4(N)
    const int grp  = lane >> 2, qid = lane & 3;

    const __half* xh = g_xh;
    const __half* wmat[3] = {
        g_wh + (size_t)0 * NEXP * D_MODEL * D_MODEL + (size_t)e * D_MODEL * D_MODEL,
        g_wh + (size_t)1 * NEXP * D_MODEL * D_MODEL + (size_t)e * D_MODEL * D_MODEL,
        g_wh + (size_t)2 * NEXP * D_MODEL * D_MODEL + (size_t)e * D_MODEL * D_MODEL };

    // ldmatrix per-lane addresses (same geometry as validated tf32 version):
    // A x4: m0=rows0-7@B0(a0), m1=rows8-15@B0(a1), m2=rows0-7@B16(a2), m3=rows8-15@B16(a3)
    const int rA = wm * 64 + ((lane >> 3) & 1) * 8 + (lane & 7);
    const int kA = (lane >> 4) * 16;
    // B x4: m0=n0-7@B0(b0), m1=n0-7@B16(b1), m2=n8-15@B0, m3=n8-15@B16
    const int rB = wn * 16 + ((lane >> 4) & 1) * 8 + (lane & 7);
    const int kB = ((lane >> 3) & 1) * 16;

    const uint32_t addrA0 = sbase + (uint32_t)rA * PITCH + kA;
    const uint32_t addrB0 = sbase + (uint32_t)(AROWS + rB) * PITCH + kB;

    float acc[3][4][2][4];
    #pragma unroll
    for (int m = 0; m < 3; m++)
        #pragma unroll
        for (int i = 0; i < 4; i++)
            #pragma unroll
            for (int j = 0; j < 2; j++)
                #pragma unroll
                for (int r = 0; r < 4; r++) acc[m][i][j][r] = 0.f;

    // producer: 2560 16B-chunks per stage (8 per 128B row), 10 per thread
    auto load_stage = [&](int kb, int st) {
        const uint32_t dst0 = sbase + st * STG_BYTES;
        const int kcol = kb * BKH;            // in halves
        #pragma unroll
        for (int it = 0; it < 10; it++) {
            int cid = tid + it * 256;
            int row = cid >> 3, c = cid & 7;
            const __half* src;
            if (row < AROWS) {
                src = xh + (size_t)(mBase + row) * D_MODEL + kcol + c * 8;
            } else {
                int r2 = row - AROWS;
                src = wmat[r2 >> 6] + (size_t)(nBase + (r2 & 63)) * D_MODEL + kcol + c * 8;
            }
            cpasync16(dst0 + (uint32_t)row * PITCH + c * 16, src);
        }
    };

    load_stage(0, 0);
    cp_commit();

    for (int kb = 0; kb < NKB; kb++) {
        if (kb + 1 < NKB) {
            load_stage(kb + 1, (kb + 1) & 1);
            cp_commit();
            cp_wait<1>();
        } else {
            cp_wait<0>();
        }
        __syncthreads();

        const uint32_t stoff = (kb & 1) * STG_BYTES;
        const uint32_t aA = addrA0 + stoff;
        const uint32_t aB = addrB0 + stoff;

        #pragma unroll
        for (int s = 0; s < 4; s++) {          // 4 k16-steps per stage
            uint32_t af[4][4];
            #pragma unroll
            for (int i = 0; i < 4; i++)
                ldsm4(af[i], aA + i * (16 * PITCH) + s * 32);
            #pragma unroll
            for (int m = 0; m < 3; m++) {
                uint32_t bf[4];
                ldsm4(bf, aB + m * (64 * PITCH) + s * 32);
                #pragma unroll
                for (int j = 0; j < 2; j++)
                    #pragma unroll
                    for (int i = 0; i < 4; i++)
                        mma_f16(acc[m][i][j], af[i], bf + 2 * j);
            }
        }
        __syncthreads();
    }

    // ---- fused epilogue (MUFU-free activations) ----
    const float* bias0 = bg + e * D_MODEL;
    const float* bias1 = bv + e * D_MODEL;
    const float* bias2 = bd + e * D_MODEL;
    #pragma unroll
    for (int i = 0; i < 4; i++)
        #pragma unroll
        for (int j = 0; j < 2; j++)
            #pragma unroll
            for (int h = 0; h < 2; h++) {
                int row = mBase + wm * 64 + i * 16 + grp + h * 8;
                int col = nBase + wn * 16 + j * 8 + qid * 2;
                float g0 = acc[0][i][j][h * 2 + 0] + __ldg(bias0 + col);
                float g1 = acc[0][i][j][h * 2 + 1] + __ldg(bias0 + col + 1);
                float v0 = acc[1][i][j][h * 2 + 0] + __ldg(bias1 + col);
                float v1 = acc[1][i][j][h * 2 + 1] + __ldg(bias1 + col + 1);
                float d0 = acc[2][i][j][h * 2 + 0] + __ldg(bias2 + col);
                float d1 = acc[2][i][j][h * 2 + 1] + __ldg(bias2 + col + 1);
                float2 xs = make_float2(sigmoid_acc(g0) * tanh_acc(v0),
                                        sigmoid_acc(g1) * tanh_acc(v1));
                float2 av = make_float2(0.001f + 0.998f * sigmoid_acc(d0),
                                        0.001f + 0.998f * sigmoid_acc(d1));
                size_t base = ((size_t)e * NTOK + row) * D_MODEL + col;
                *(float2*)(g_xs + base) = xs;
                *(float2*)(g_a  + base) = av;
            }
}

// ---------------------------------------------------------------------------
// Chunked linear scan
// ---------------------------------------------------------------------------
__global__ __launch_bounds__(256) void scan_pass1() {
    int d  = blockIdx.x * 256 + threadIdx.x;
    int c  = blockIdx.y;
    int eb = blockIdx.z;
    size_t base = ((size_t)eb * S_LEN + c * CHUNK) * D_MODEL + d;
    float A = 1.f, X = 0.f;
    #pragma unroll 8
    for (int t = 0; t < CHUNK; t++) {
        float a  = g_a [base + (size_t)t * D_MODEL];
        float xv = g_xs[base + (size_t)t * D_MODEL];
        X = fmaf(a, X, xv);
        A *= a;
    }
    int sidx = (eb * NCHUNK + c) * D_MODEL + d;
    g_sumA[sidx] = A;
    g_sumX[sidx] = X;
}

__global__ __launch_bounds__(256) void scan_pass2() {
    int idx = blockIdx.x * 256 + threadIdx.x;
    int eb = idx >> 10, d = idx & 1023;
    float h = 0.f;
    for (int c = 0; c < NCHUNK; c++) {
        int s = (eb * NCHUNK + c) * D_MODEL + d;
        g_hstart[s] = h;
        h = fmaf(g_sumA[s], h, g_sumX[s]);
    }
}

__global__ __launch_bounds__(256) void scan_pass3(float* __restrict__ out) {
    int d = blockIdx.x * 256 + threadIdx.x;
    int c = blockIdx.y;
    int b = blockIdx.z;
    __shared__ float ws[CHUNK * NEXP];
    int t0 = c * CHUNK;
    ws[threadIdx.x] = g_w[(size_t)(b * S_LEN + t0) * NEXP + threadIdx.x];
    __syncthreads();

    float  h[NEXP];
    size_t xbase[NEXP];
    #pragma unroll
    for (int e = 0; e < NEXP; e++) {
        int eb = e * BATCH + b;
        h[e]     = g_hstart[(eb * NCHUNK + c) * D_MODEL + d];
        xbase[e] = ((size_t)eb * S_LEN + t0) * D_MODEL + d;
    }
    float* op = out + ((size_t)(b * S_LEN + t0)) * D_MODEL + d;
    #pragma unroll 4
    for (int t = 0; t < CHUNK; t++) {
        float acc = 0.f;
        #pragma unroll
        for (int e = 0; e < NEXP; e++) {
            size_t idx = xbase[e] + (size_t)t * D_MODEL;
            h[e] = fmaf(g_a[idx], h[e], g_xs[idx]);
            acc  = fmaf(ws[t * NEXP + e], h[e], acc);
        }
        op[(size_t)t * D_MODEL] = acc;
    }
}

// ---------------------------------------------------------------------------
// Launch
// ---------------------------------------------------------------------------
extern "C" void kernel_launch(void* const* d_in, const int* in_sizes, int n_in,
                              void* d_out, int out_size) {
    const float* x     = (const float*)d_in[0];
    const float* Wg    = (const float*)d_in[1];
    const float* bg    = (const float*)d_in[2];
    const float* Wv    = (const float*)d_in[3];
    const float* bv    = (const float*)d_in[4];
    const float* Wd    = (const float*)d_in[5];
    const float* bd    = (const float*)d_in[6];
    const float* Wgate = (const float*)d_in[7];
    float* out = (float*)d_out;

    cudaFuncSetAttribute(proj_gemm_kernel,
                         cudaFuncAttributeMaxDynamicSharedMemorySize, SMEM_BYTES);

    __half* xh_p; cudaGetSymbolAddress((void**)&xh_p, g_xh);
    __half* wh_p; cudaGetSymbolAddress((void**)&wh_p, g_wh);
    const size_t WSTRIDE = (size_t)NEXP * D_MODEL * D_MODEL;   // floats per W tensor

    f2h_kernel<<<(NTOK * D_MODEL / 4) / 256, 256>>>((const float4*)x, (__half2*)xh_p);
    f2h_kernel<<<(int)(WSTRIDE / 4) / 256, 256>>>((const float4*)Wg, (__half2*)(wh_p + 0 * WSTRIDE));
    f2h_kernel<<<(int)(WSTRIDE / 4) / 256, 256>>>((const float4*)Wv, (__half2*)(wh_p + 1 * WSTRIDE));
    f2h_kernel<<<(int)(WSTRIDE / 4) / 256, 256>>>((const float4*)Wd, (__half2*)(wh_p + 2 * WSTRIDE));

    router_kernel<<<(NTOK * 32) / 256, 256>>>(x, Wgate);

    proj_gemm_kernel<<<dim3(NTOK / BM, D_MODEL / BN, NEXP), 256, SMEM_BYTES>>>(bg, bv, bd);

    scan_pass1<<<dim3(D_MODEL / 256, NCHUNK, NEXP * BATCH), 256>>>();
    scan_pass2<<<(NEXP * BATCH * D_MODEL) / 256, 256>>>();
    scan_pass3<<<dim3(D_MODEL / 256, NCHUNK, BATCH), 256>>>(out);
}

// round 9
// speedup vs baseline: 4.2305x; 1.0618x over previous
#include <cuda_runtime.h>
#include <cuda_fp16.h>
#include <cstdint>
#include <math.h>

// ---------------------------------------------------------------------------
// Problem constants
// ---------------------------------------------------------------------------
#define D_MODEL 1024
#define S_LEN   4096
#define BATCH   4
#define NEXP    4
#define NTOK    16384
#define CHUNK   64
#define NCHUNK  64

// GEMM tiling (fp16 mma.m16n8k16)
#define BM 128
#define BN 64
#define BKH 64                      // K halves per stage (=128 bytes/row)
#define NKB (D_MODEL / BKH)         // 16 stages
#define PITCH 144                   // bytes per smem row (128B data + 16B pad)
#define AROWS BM                    // 128
#define BROWS (3 * BN)              // 192
#define STG_ROWS (AROWS + BROWS)    // 320
#define STG_BYTES (STG_ROWS * PITCH)        // 46080
#define SMEM_BYTES (2 * STG_BYTES)          // 92160

// ---------------------------------------------------------------------------
// Scratch (device globals; no dynamic allocation allowed)
// ---------------------------------------------------------------------------
__device__ __half g_xs_h[(size_t)NEXP * NTOK * D_MODEL];         // fp16 sigmoid(g)*tanh(v)
__device__ __half g_a_h [(size_t)NEXP * NTOK * D_MODEL];         // fp16 decay a
__device__ float g_sumA  [NEXP * BATCH * NCHUNK * D_MODEL];
__device__ float g_sumX  [NEXP * BATCH * NCHUNK * D_MODEL];
__device__ float g_hstart[NEXP * BATCH * NCHUNK * D_MODEL];
__device__ float g_w[NTOK * NEXP];
__device__ __half g_xh[(size_t)NTOK * D_MODEL];                  // fp16 x
__device__ __half g_wh[(size_t)3 * NEXP * D_MODEL * D_MODEL];    // fp16 W (mat-major)

// ---------------------------------------------------------------------------
// Helpers
// ---------------------------------------------------------------------------
// exp2 on FMA/ALU pipes only (no MUFU): rel err ~1e-6
__device__ __forceinline__ float exp2_fma(float t) {
    float r  = t + 12582912.0f;              // round-to-int (2^23 * 1.5)
    int   ir = __float_as_int(r);
    float f  = t - (r - 12582912.0f);        // f in [-0.5, 0.5]
    float p  = 1.3333558146e-3f;
    p = fmaf(p, f, 9.6180886130e-3f);
    p = fmaf(p, f, 5.5504108664e-2f);
    p = fmaf(p, f, 2.4022650696e-1f);
    p = fmaf(p, f, 6.9314718056e-1f);
    p = fmaf(p, f, 1.0f);
    float s = __int_as_float((ir << 23) + 0x3F800000);
    return s * p;
}
__device__ __forceinline__ float frcp_(float x) {
    float y = __uint_as_float(0x7EF311C3u - __float_as_uint(x));
    y = y * (2.0f - x * y);
    y = y * (2.0f - x * y);
    y = y * (2.0f - x * y);
    return y;
}
__device__ __forceinline__ float sigmoid_acc(float z) {
    z = fminf(fmaxf(z, -30.0f), 30.0f);
    return frcp_(1.0f + exp2_fma(-1.4426950408889634f * z));
}
__device__ __forceinline__ float tanh_acc(float v) {
    v = fminf(fmaxf(v, -9.0f), 9.0f);
    float t = exp2_fma(2.8853900817779268f * v);
    return (t - 1.0f) * frcp_(t + 1.0f);
}

__device__ __forceinline__ void mma_f16(float* c, const uint32_t* a, const uint32_t* b) {
    asm volatile(
        "mma.sync.aligned.m16n8k16.row.col.f32.f16.f16.f32 "
        "{%0,%1,%2,%3}, {%4,%5,%6,%7}, {%8,%9}, {%0,%1,%2,%3};\n"
        : "+f"(c[0]), "+f"(c[1]), "+f"(c[2]), "+f"(c[3])
        : "r"(a[0]), "r"(a[1]), "r"(a[2]), "r"(a[3]), "r"(b[0]), "r"(b[1]));
}

__device__ __forceinline__ void ldsm4(uint32_t* r, uint32_t addr) {
    asm volatile(
        "ldmatrix.sync.aligned.m8n8.x4.shared.b16 {%0,%1,%2,%3}, [%4];"
        : "=r"(r[0]), "=r"(r[1]), "=r"(r[2]), "=r"(r[3]) : "r"(addr));
}

__device__ __forceinline__ void cpasync16(uint32_t dst_smem, const void* src) {
    asm volatile("cp.async.cg.shared.global [%0], [%1], 16;" :: "r"(dst_smem), "l"(src));
}
__device__ __forceinline__ void cp_commit() { asm volatile("cp.async.commit_group;"); }
template <int N>
__device__ __forceinline__ void cp_wait() { asm volatile("cp.async.wait_group %0;" :: "n"(N)); }

// ---------------------------------------------------------------------------
// Merged pre-pass: fp32 -> fp16 for x, Wg, Wv, Wd in ONE kernel
// regions (in float4 units): [0,NX4) -> x ; then 3 W regions of NW4 each
// ---------------------------------------------------------------------------
#define NX4 ((NTOK * D_MODEL) / 4)
#define NW4 ((NEXP * D_MODEL * D_MODEL) / 4)

__global__ __launch_bounds__(256) void f2h_all_kernel(
    const float4* __restrict__ x, const float4* __restrict__ Wg,
    const float4* __restrict__ Wv, const float4* __restrict__ Wd)
{
    int i = blockIdx.x * 256 + threadIdx.x;
    const float4* src;
    __half2* dst;
    int off;
    if (i < NX4) {
        src = x;   dst = (__half2*)g_xh;               off = i;
    } else if (i < NX4 + NW4) {
        src = Wg;  dst = (__half2*)g_wh;               off = i - NX4;
    } else if (i < NX4 + 2 * NW4) {
        src = Wv;  dst = (__half2*)g_wh + 2 * NW4;     off = i - NX4 - NW4;
    } else {
        src = Wd;  dst = (__half2*)g_wh + 4 * NW4;     off = i - NX4 - 2 * NW4;
    }
    float4 v = src[off];
    dst[2 * off]     = __floats2half2_rn(v.x, v.y);
    dst[2 * off + 1] = __floats2half2_rn(v.z, v.w);
}

// ---------------------------------------------------------------------------
// Router
// ---------------------------------------------------------------------------
__global__ __launch_bounds__(256) void router_kernel(const float* __restrict__ x,
                                                     const float* __restrict__ Wgate) {
    int gtid  = blockIdx.x * 256 + threadIdx.x;
    int token = gtid >> 5;
    int lane  = gtid & 31;
    const float* xr = x + (size_t)token * D_MODEL;

    float a0 = 0.f, a1 = 0.f, a2 = 0.f, a3 = 0.f;
    #pragma unroll 8
    for (int k = lane; k < D_MODEL; k += 32) {
        float xv = xr[k];
        a0 = fmaf(xv, Wgate[k],               a0);
        a1 = fmaf(xv, Wgate[D_MODEL + k],     a1);
        a2 = fmaf(xv, Wgate[2 * D_MODEL + k], a2);
        a3 = fmaf(xv, Wgate[3 * D_MODEL + k], a3);
    }
    #pragma unroll
    for (int o = 16; o; o >>= 1) {
        a0 += __shfl_down_sync(0xffffffffu, a0, o);
        a1 += __shfl_down_sync(0xffffffffu, a1, o);
        a2 += __shfl_down_sync(0xffffffffu, a2, o);
        a3 += __shfl_down_sync(0xffffffffu, a3, o);
    }
    if (lane == 0) {
        float l[4] = {a0, a1, a2, a3};
        int i0 = 0;
        #pragma unroll
        for (int i = 1; i < 4; i++) if (l[i] > l[i0]) i0 = i;
        int i1 = -1;
        #pragma unroll
        for (int i = 0; i < 4; i++) if (i != i0 && (i1 < 0 || l[i] > l[i1])) i1 = i;
        float ex = __expf(l[i1] - l[i0]);
        float den = 1.0f + ex;
        float wv[4] = {0.f, 0.f, 0.f, 0.f};
        wv[i0] = 1.0f / den;
        wv[i1] = ex / den;
        *(float4*)(g_w + (size_t)token * NEXP) = make_float4(wv[0], wv[1], wv[2], wv[3]);
    }
}

// ---------------------------------------------------------------------------
// Fused projection GEMM: fp16 mma.m16n8k16 + ldmatrix, 2-stage cp.async.
// CTA 128(M) x 64(N) x 3 matrices. 8 warps = 2(M) x 4(N), warp tile 64x16.
// Epilogue: FMA-pipe activations, fp16 outputs.
// ---------------------------------------------------------------------------
__global__ __launch_bounds__(256, 2) void proj_gemm_kernel(
    const float* __restrict__ bg, const float* __restrict__ bv,
    const float* __restrict__ bd)
{
    extern __shared__ char smem[];
    const uint32_t sbase = (uint32_t)__cvta_generic_to_shared(smem);

    const int e     = blockIdx.z;
    const int mBase = blockIdx.x * BM;
    const int nBase = blockIdx.y * BN;

    const int tid  = threadIdx.x;
    const int wid  = tid >> 5, lane = tid & 31;
    const int wm   = wid >> 2, wn = wid & 3;   // 2(M) x 4(N)
    const int grp  = lane >> 2, qid = lane & 3;

    const __half* xh = g_xh;
    const __half* wmat[3] = {
        g_wh + (size_t)0 * NEXP * D_MODEL * D_MODEL + (size_t)e * D_MODEL * D_MODEL,
        g_wh + (size_t)1 * NEXP * D_MODEL * D_MODEL + (size_t)e * D_MODEL * D_MODEL,
        g_wh + (size_t)2 * NEXP * D_MODEL * D_MODEL + (size_t)e * D_MODEL * D_MODEL };

    const int rA = wm * 64 + ((lane >> 3) & 1) * 8 + (lane & 7);
    const int kA = (lane >> 4) * 16;
    const int rB = wn * 16 + ((lane >> 4) & 1) * 8 + (lane & 7);
    const int kB = ((lane >> 3) & 1) * 16;

    const uint32_t addrA0 = sbase + (uint32_t)rA * PITCH + kA;
    const uint32_t addrB0 = sbase + (uint32_t)(AROWS + rB) * PITCH + kB;

    float acc[3][4][2][4];
    #pragma unroll
    for (int m = 0; m < 3; m++)
        #pragma unroll
        for (int i = 0; i < 4; i++)
            #pragma unroll
            for (int j = 0; j < 2; j++)
                #pragma unroll
                for (int r = 0; r < 4; r++) acc[m][i][j][r] = 0.f;

    auto load_stage = [&](int kb, int st) {
        const uint32_t dst0 = sbase + st * STG_BYTES;
        const int kcol = kb * BKH;
        #pragma unroll
        for (int it = 0; it < 10; it++) {
            int cid = tid + it * 256;
            int row = cid >> 3, c = cid & 7;
            const __half* src;
            if (row < AROWS) {
                src = xh + (size_t)(mBase + row) * D_MODEL + kcol + c * 8;
            } else {
                int r2 = row - AROWS;
                src = wmat[r2 >> 6] + (size_t)(nBase + (r2 & 63)) * D_MODEL + kcol + c * 8;
            }
            cpasync16(dst0 + (uint32_t)row * PITCH + c * 16, src);
        }
    };

    load_stage(0, 0);
    cp_commit();

    for (int kb = 0; kb < NKB; kb++) {
        if (kb + 1 < NKB) {
            load_stage(kb + 1, (kb + 1) & 1);
            cp_commit();
            cp_wait<1>();
        } else {
            cp_wait<0>();
        }
        __syncthreads();

        const uint32_t stoff = (kb & 1) * STG_BYTES;
        const uint32_t aA = addrA0 + stoff;
        const uint32_t aB = addrB0 + stoff;

        #pragma unroll
        for (int s = 0; s < 4; s++) {
            uint32_t af[4][4];
            #pragma unroll
            for (int i = 0; i < 4; i++)
                ldsm4(af[i], aA + i * (16 * PITCH) + s * 32);
            #pragma unroll
            for (int m = 0; m < 3; m++) {
                uint32_t bf[4];
                ldsm4(bf, aB + m * (64 * PITCH) + s * 32);
                #pragma unroll
                for (int j = 0; j < 2; j++)
                    #pragma unroll
                    for (int i = 0; i < 4; i++)
                        mma_f16(acc[m][i][j], af[i], bf + 2 * j);
            }
        }
        __syncthreads();
    }

    // ---- fused epilogue: activations -> fp16 xs / a ----
    const float* bias0 = bg + e * D_MODEL;
    const float* bias1 = bv + e * D_MODEL;
    const float* bias2 = bd + e * D_MODEL;
    #pragma unroll
    for (int i = 0; i < 4; i++)
        #pragma unroll
        for (int j = 0; j < 2; j++)
            #pragma unroll
            for (int h = 0; h < 2; h++) {
                int row = mBase + wm * 64 + i * 16 + grp + h * 8;
                int col = nBase + wn * 16 + j * 8 + qid * 2;
                float g0 = acc[0][i][j][h * 2 + 0] + __ldg(bias0 + col);
                float g1 = acc[0][i][j][h * 2 + 1] + __ldg(bias0 + col + 1);
                float v0 = acc[1][i][j][h * 2 + 0] + __ldg(bias1 + col);
                float v1 = acc[1][i][j][h * 2 + 1] + __ldg(bias1 + col + 1);
                float d0 = acc[2][i][j][h * 2 + 0] + __ldg(bias2 + col);
                float d1 = acc[2][i][j][h * 2 + 1] + __ldg(bias2 + col + 1);
                __half2 xsh = __floats2half2_rn(sigmoid_acc(g0) * tanh_acc(v0),
                                                sigmoid_acc(g1) * tanh_acc(v1));
                __half2 avh = __floats2half2_rn(0.001f + 0.998f * sigmoid_acc(d0),
                                                0.001f + 0.998f * sigmoid_acc(d1));
                size_t base = ((size_t)e * NTOK + row) * D_MODEL + col;
                *(__half2*)(g_xs_h + base) = xsh;
                *(__half2*)(g_a_h  + base) = avh;
            }
}

// ---------------------------------------------------------------------------
// Chunked linear scan (fp16 inputs, fp32 state)
// ---------------------------------------------------------------------------
__global__ __launch_bounds__(256) void scan_pass1() {
    int d2 = blockIdx.x * 256 + threadIdx.x;        // channel pair 0..511
    int c  = blockIdx.y;
    int eb = blockIdx.z;
    size_t base = ((size_t)eb * S_LEN + c * CHUNK) * D_MODEL + 2 * d2;
    float2 A = make_float2(1.f, 1.f), X = make_float2(0.f, 0.f);
    #pragma unroll 8
    for (int t = 0; t < CHUNK; t++) {
        float2 a  = __half22float2(*(const __half2*)(g_a_h  + base + (size_t)t * D_MODEL));
        float2 xv = __half22float2(*(const __half2*)(g_xs_h + base + (size_t)t * D_MODEL));
        X.x = fmaf(a.x, X.x, xv.x);
        X.y = fmaf(a.y, X.y, xv.y);
        A.x *= a.x;
        A.y *= a.y;
    }
    int sidx = (eb * NCHUNK + c) * D_MODEL + 2 * d2;
    *(float2*)(g_sumA + sidx) = A;
    *(float2*)(g_sumX + sidx) = X;
}

__global__ __launch_bounds__(256) void scan_pass2() {
    int idx = blockIdx.x * 256 + threadIdx.x;
    int eb = idx >> 10, d = idx & 1023;
    float h = 0.f;
    for (int c = 0; c < NCHUNK; c++) {
        int s = (eb * NCHUNK + c) * D_MODEL + d;
        g_hstart[s] = h;
        h = fmaf(g_sumA[s], h, g_sumX[s]);
    }
}

__global__ __launch_bounds__(256) void scan_pass3(float* __restrict__ out) {
    int d2 = blockIdx.x * 256 + threadIdx.x;        // channel pair 0..511
    int c  = blockIdx.y;
    int b  = blockIdx.z;
    __shared__ float ws[CHUNK * NEXP];
    int t0 = c * CHUNK;
    ws[threadIdx.x] = g_w[(size_t)(b * S_LEN + t0) * NEXP + threadIdx.x];
    __syncthreads();

    float2 h[NEXP];
    size_t xbase[NEXP];
    #pragma unroll
    for (int e = 0; e < NEXP; e++) {
        int eb = e * BATCH + b;
        h[e] = *(const float2*)(g_hstart + (eb * NCHUNK + c) * D_MODEL + 2 * d2);
        xbase[e] = ((size_t)eb * S_LEN + t0) * D_MODEL + 2 * d2;
    }
    float* op = out + ((size_t)(b * S_LEN + t0)) * D_MODEL + 2 * d2;
    #pragma unroll 4
    for (int t = 0; t < CHUNK; t++) {
        float2 acc = make_float2(0.f, 0.f);
        #pragma unroll
        for (int e = 0; e < NEXP; e++) {
            size_t idx = xbase[e] + (size_t)t * D_MODEL;
            float2 a  = __half22float2(*(const __half2*)(g_a_h  + idx));
            float2 xv = __half22float2(*(const __half2*)(g_xs_h + idx));
            h[e].x = fmaf(a.x, h[e].x, xv.x);
            h[e].y = fmaf(a.y, h[e].y, xv.y);
            float w = ws[t * NEXP + e];
            acc.x = fmaf(w, h[e].x, acc.x);
            acc.y = fmaf(w, h[e].y, acc.y);
        }
        *(float2*)(op + (size_t)t * D_MODEL) = acc;
    }
}

// ---------------------------------------------------------------------------
// Launch
// ---------------------------------------------------------------------------
extern "C" void kernel_launch(void* const* d_in, const int* in_sizes, int n_in,
                              void* d_out, int out_size) {
    const float* x     = (const float*)d_in[0];
    const float* Wg    = (const float*)d_in[1];
    const float* bg    = (const float*)d_in[2];
    const float* Wv    = (const float*)d_in[3];
    const float* bv    = (const float*)d_in[4];
    const float* Wd    = (const float*)d_in[5];
    const float* bd    = (const float*)d_in[6];
    const float* Wgate = (const float*)d_in[7];
    float* out = (float*)d_out;

    cudaFuncSetAttribute(proj_gemm_kernel,
                         cudaFuncAttributeMaxDynamicSharedMemorySize, SMEM_BYTES);

    // Merged fp32->fp16 conversion (x + Wg + Wv + Wd)
    f2h_all_kernel<<<(NX4 + 3 * NW4) / 256, 256>>>(
        (const float4*)x, (const float4*)Wg, (const float4*)Wv, (const float4*)Wd);

    router_kernel<<<(NTOK * 32) / 256, 256>>>(x, Wgate);

    proj_gemm_kernel<<<dim3(NTOK / BM, D_MODEL / BN, NEXP), 256, SMEM_BYTES>>>(bg, bv, bd);

    scan_pass1<<<dim3(D_MODEL / 2 / 256, NCHUNK, NEXP * BATCH), 256>>>();
    scan_pass2<<<(NEXP * BATCH * D_MODEL) / 256, 256>>>();
    scan_pass3<<<dim3(D_MODEL / 2 / 256, NCHUNK, BATCH), 256>>>(out);
}

// round 10
// speedup vs baseline: 4.3926x; 1.0383x over previous
#include <cuda_runtime.h>
#include <cuda_fp16.h>
#include <cstdint>
#include <math.h>

// ---------------------------------------------------------------------------
// Problem constants
// ---------------------------------------------------------------------------
#define D_MODEL 1024
#define S_LEN   4096
#define BATCH   4
#define NEXP    4
#define NTOK    16384
#define CHUNK   64
#define NCHUNK  64

// GEMM tiling (fp16 mma.m16n8k16)
#define BM 128
#define BN 64
#define BKH 64                      // K halves per stage (=128 bytes/row)
#define NKB (D_MODEL / BKH)         // 16 stages
#define PITCH 144                   // bytes per smem row (128B data + 16B pad)
#define AROWS BM                    // 128
#define BROWS (3 * BN)              // 192
#define STG_ROWS (AROWS + BROWS)    // 320
#define STG_BYTES (STG_ROWS * PITCH)        // 46080
#define SMEM_BYTES (2 * STG_BYTES)          // 92160

// ---------------------------------------------------------------------------
// Scratch (device globals; no dynamic allocation allowed)
// ---------------------------------------------------------------------------
__device__ __half g_xs_h[(size_t)NEXP * NTOK * D_MODEL];         // fp16 sigmoid(g)*tanh(v)
__device__ __half g_a_h [(size_t)NEXP * NTOK * D_MODEL];         // fp16 decay a
__device__ float2 g_sumAX[NEXP * BATCH * NCHUNK * D_MODEL];      // per-chunk (prodA, scanX)
__device__ float  g_hstart[NEXP * BATCH * NCHUNK * D_MODEL];
__device__ float  g_w[NTOK * NEXP];
__device__ __half g_xh[(size_t)NTOK * D_MODEL];                  // fp16 x (written by router)
__device__ __half g_wh[(size_t)3 * NEXP * D_MODEL * D_MODEL];    // fp16 W (mat-major)

// ---------------------------------------------------------------------------
// Helpers
// ---------------------------------------------------------------------------
// exp2 on FMA/ALU pipes only (no MUFU): rel err ~1e-6
__device__ __forceinline__ float exp2_fma(float t) {
    float r  = t + 12582912.0f;              // round-to-int (2^23 * 1.5)
    int   ir = __float_as_int(r);
    float f  = t - (r - 12582912.0f);        // f in [-0.5, 0.5]
    float p  = 1.3333558146e-3f;
    p = fmaf(p, f, 9.6180886130e-3f);
    p = fmaf(p, f, 5.5504108664e-2f);
    p = fmaf(p, f, 2.4022650696e-1f);
    p = fmaf(p, f, 6.9314718056e-1f);
    p = fmaf(p, f, 1.0f);
    float s = __int_as_float((ir << 23) + 0x3F800000);
    return s * p;
}
__device__ __forceinline__ float frcp_(float x) {
    float y = __uint_as_float(0x7EF311C3u - __float_as_uint(x));
    y = y * (2.0f - x * y);
    y = y * (2.0f - x * y);
    y = y * (2.0f - x * y);
    return y;
}
__device__ __forceinline__ float sigmoid_acc(float z) {
    z = fminf(fmaxf(z, -30.0f), 30.0f);
    return frcp_(1.0f + exp2_fma(-1.4426950408889634f * z));
}
__device__ __forceinline__ float tanh_acc(float v) {
    v = fminf(fmaxf(v, -9.0f), 9.0f);
    float t = exp2_fma(2.8853900817779268f * v);
    return (t - 1.0f) * frcp_(t + 1.0f);
}

__device__ __forceinline__ void mma_f16(float* c, const uint32_t* a, const uint32_t* b) {
    asm volatile(
        "mma.sync.aligned.m16n8k16.row.col.f32.f16.f16.f32 "
        "{%0,%1,%2,%3}, {%4,%5,%6,%7}, {%8,%9}, {%0,%1,%2,%3};\n"
        : "+f"(c[0]), "+f"(c[1]), "+f"(c[2]), "+f"(c[3])
        : "r"(a[0]), "r"(a[1]), "r"(a[2]), "r"(a[3]), "r"(b[0]), "r"(b[1]));
}

__device__ __forceinline__ void ldsm4(uint32_t* r, uint32_t addr) {
    asm volatile(
        "ldmatrix.sync.aligned.m8n8.x4.shared.b16 {%0,%1,%2,%3}, [%4];"
        : "=r"(r[0]), "=r"(r[1]), "=r"(r[2]), "=r"(r[3]) : "r"(addr));
}

__device__ __forceinline__ void cpasync16(uint32_t dst_smem, const void* src) {
    asm volatile("cp.async.cg.shared.global [%0], [%1], 16;" :: "r"(dst_smem), "l"(src));
}
__device__ __forceinline__ void cp_commit() { asm volatile("cp.async.commit_group;"); }
template <int N>
__device__ __forceinline__ void cp_wait() { asm volatile("cp.async.wait_group %0;" :: "n"(N)); }

// ---------------------------------------------------------------------------
// Pre-pass: fp32 -> fp16 for Wg, Wv, Wd (x handled inside router)
// ---------------------------------------------------------------------------
#define NW4 ((NEXP * D_MODEL * D_MODEL) / 4)

__global__ __launch_bounds__(256) void f2h_w_kernel(
    const float4* __restrict__ Wg, const float4* __restrict__ Wv,
    const float4* __restrict__ Wd)
{
    int i = blockIdx.x * 256 + threadIdx.x;
    const float4* src;
    __half2* dst;
    int off;
    if (i < NW4) {
        src = Wg;  dst = (__half2*)g_wh;               off = i;
    } else if (i < 2 * NW4) {
        src = Wv;  dst = (__half2*)g_wh + 2 * NW4;     off = i - NW4;
    } else {
        src = Wd;  dst = (__half2*)g_wh + 4 * NW4;     off = i - 2 * NW4;
    }
    float4 v = src[off];
    dst[2 * off]     = __floats2half2_rn(v.x, v.y);
    dst[2 * off + 1] = __floats2half2_rn(v.z, v.w);
}

// ---------------------------------------------------------------------------
// Router (also converts x -> fp16 while it has the data)
// ---------------------------------------------------------------------------
__global__ __launch_bounds__(256) void router_kernel(const float* __restrict__ x,
                                                     const float* __restrict__ Wgate) {
    int gtid  = blockIdx.x * 256 + threadIdx.x;
    int token = gtid >> 5;
    int lane  = gtid & 31;
    const float* xr = x + (size_t)token * D_MODEL;
    __half* xo = g_xh + (size_t)token * D_MODEL;

    float a0 = 0.f, a1 = 0.f, a2 = 0.f, a3 = 0.f;
    #pragma unroll 8
    for (int k = lane; k < D_MODEL; k += 32) {
        float xv = xr[k];
        xo[k] = __float2half_rn(xv);
        a0 = fmaf(xv, Wgate[k],               a0);
        a1 = fmaf(xv, Wgate[D_MODEL + k],     a1);
        a2 = fmaf(xv, Wgate[2 * D_MODEL + k], a2);
        a3 = fmaf(xv, Wgate[3 * D_MODEL + k], a3);
    }
    #pragma unroll
    for (int o = 16; o; o >>= 1) {
        a0 += __shfl_down_sync(0xffffffffu, a0, o);
        a1 += __shfl_down_sync(0xffffffffu, a1, o);
        a2 += __shfl_down_sync(0xffffffffu, a2, o);
        a3 += __shfl_down_sync(0xffffffffu, a3, o);
    }
    if (lane == 0) {
        float l[4] = {a0, a1, a2, a3};
        int i0 = 0;
        #pragma unroll
        for (int i = 1; i < 4; i++) if (l[i] > l[i0]) i0 = i;
        int i1 = -1;
        #pragma unroll
        for (int i = 0; i < 4; i++) if (i != i0 && (i1 < 0 || l[i] > l[i1])) i1 = i;
        float ex = __expf(l[i1] - l[i0]);
        float den = 1.0f + ex;
        float wv[4] = {0.f, 0.f, 0.f, 0.f};
        wv[i0] = 1.0f / den;
        wv[i1] = ex / den;
        *(float4*)(g_w + (size_t)token * NEXP) = make_float4(wv[0], wv[1], wv[2], wv[3]);
    }
}

// ---------------------------------------------------------------------------
// Fused projection GEMM: fp16 mma.m16n8k16 + ldmatrix, 2-stage cp.async.
// CTA 128(M) x 64(N) x 3 matrices. 8 warps = 2(M) x 4(N), warp tile 64x16.
// Epilogue: activations -> fp16 xs/a, PLUS fused per-chunk scan summary
// (warp m-tile = 64 tokens = exactly one scan chunk).
// ---------------------------------------------------------------------------
__global__ __launch_bounds__(256, 2) void proj_gemm_kernel(
    const float* __restrict__ bg, const float* __restrict__ bv,
    const float* __restrict__ bd)
{
    extern __shared__ char smem[];
    const uint32_t sbase = (uint32_t)__cvta_generic_to_shared(smem);

    const int e     = blockIdx.z;
    const int mBase = blockIdx.x * BM;
    const int nBase = blockIdx.y * BN;

    const int tid  = threadIdx.x;
    const int wid  = tid >> 5, lane = tid & 31;
    const int wm   = wid >> 2, wn = wid & 3;   // 2(M) x 4(N)
    const int grp  = lane >> 2, qid = lane & 3;

    const __half* xh = g_xh;
    const __half* wmat[3] = {
        g_wh + (size_t)0 * NEXP * D_MODEL * D_MODEL + (size_t)e * D_MODEL * D_MODEL,
        g_wh + (size_t)1 * NEXP * D_MODEL * D_MODEL + (size_t)e * D_MODEL * D_MODEL,
        g_wh + (size_t)2 * NEXP * D_MODEL * D_MODEL + (size_t)e * D_MODEL * D_MODEL };

    const int rA = wm * 64 + ((lane >> 3) & 1) * 8 + (lane & 7);
    const int kA = (lane >> 4) * 16;
    const int rB = wn * 16 + ((lane >> 4) & 1) * 8 + (lane & 7);
    const int kB = ((lane >> 3) & 1) * 16;

    const uint32_t addrA0 = sbase + (uint32_t)rA * PITCH + kA;
    const uint32_t addrB0 = sbase + (uint32_t)(AROWS + rB) * PITCH + kB;

    float acc[3][4][2][4];
    #pragma unroll
    for (int m = 0; m < 3; m++)
        #pragma unroll
        for (int i = 0; i < 4; i++)
            #pragma unroll
            for (int j = 0; j < 2; j++)
                #pragma unroll
                for (int r = 0; r < 4; r++) acc[m][i][j][r] = 0.f;

    auto load_stage = [&](int kb, int st) {
        const uint32_t dst0 = sbase + st * STG_BYTES;
        const int kcol = kb * BKH;
        #pragma unroll
        for (int it = 0; it < 10; it++) {
            int cid = tid + it * 256;
            int row = cid >> 3, c = cid & 7;
            const __half* src;
            if (row < AROWS) {
                src = xh + (size_t)(mBase + row) * D_MODEL + kcol + c * 8;
            } else {
                int r2 = row - AROWS;
                src = wmat[r2 >> 6] + (size_t)(nBase + (r2 & 63)) * D_MODEL + kcol + c * 8;
            }
            cpasync16(dst0 + (uint32_t)row * PITCH + c * 16, src);
        }
    };

    load_stage(0, 0);
    cp_commit();

    for (int kb = 0; kb < NKB; kb++) {
        if (kb + 1 < NKB) {
            load_stage(kb + 1, (kb + 1) & 1);
            cp_commit();
            cp_wait<1>();
        } else {
            cp_wait<0>();
        }
        __syncthreads();

        const uint32_t stoff = (kb & 1) * STG_BYTES;
        const uint32_t aA = addrA0 + stoff;
        const uint32_t aB = addrB0 + stoff;

        #pragma unroll
        for (int s = 0; s < 4; s++) {
            uint32_t af[4][4];
            #pragma unroll
            for (int i = 0; i < 4; i++)
                ldsm4(af[i], aA + i * (16 * PITCH) + s * 32);
            #pragma unroll
            for (int m = 0; m < 3; m++) {
                uint32_t bf[4];
                ldsm4(bf, aB + m * (64 * PITCH) + s * 32);
                #pragma unroll
                for (int j = 0; j < 2; j++)
                    #pragma unroll
                    for (int i = 0; i < 4; i++)
                        mma_f16(acc[m][i][j], af[i], bf + 2 * j);
            }
        }
        __syncthreads();
    }
    // After final __syncthreads all stage smem is dead -> reuse as scan buffer.
    // Per-warp buffer: 64 t x 16 d __half2 (a, x) = 4 KB at smem + wid*4096.
    __half2* buf = (__half2*)(smem + wid * 4096);

    // ---- fused epilogue: activations -> fp16 xs/a (gmem) + smem (a,x) tile ----
    const float* bias0 = bg + e * D_MODEL;
    const float* bias1 = bv + e * D_MODEL;
    const float* bias2 = bd + e * D_MODEL;
    #pragma unroll
    for (int i = 0; i < 4; i++)
        #pragma unroll
        for (int j = 0; j < 2; j++)
            #pragma unroll
            for (int h = 0; h < 2; h++) {
                int tloc = i * 16 + h * 8 + grp;             // 0..63 within chunk
                int cloc = j * 8 + qid * 2;                  // 0..14 within warp cols
                int row = mBase + wm * 64 + tloc;
                int col = nBase + wn * 16 + cloc;
                float g0 = acc[0][i][j][h * 2 + 0] + __ldg(bias0 + col);
                float g1 = acc[0][i][j][h * 2 + 1] + __ldg(bias0 + col + 1);
                float v0 = acc[1][i][j][h * 2 + 0] + __ldg(bias1 + col);
                float v1 = acc[1][i][j][h * 2 + 1] + __ldg(bias1 + col + 1);
                float d0 = acc[2][i][j][h * 2 + 0] + __ldg(bias2 + col);
                float d1 = acc[2][i][j][h * 2 + 1] + __ldg(bias2 + col + 1);
                float xs0 = sigmoid_acc(g0) * tanh_acc(v0);
                float xs1 = sigmoid_acc(g1) * tanh_acc(v1);
                float av0 = 0.001f + 0.998f * sigmoid_acc(d0);
                float av1 = 0.001f + 0.998f * sigmoid_acc(d1);
                __half2 xsh = __floats2half2_rn(xs0, xs1);
                __half2 avh = __floats2half2_rn(av0, av1);
                size_t base = ((size_t)e * NTOK + row) * D_MODEL + col;
                *(__half2*)(g_xs_h + base) = xsh;
                *(__half2*)(g_a_h  + base) = avh;
                // smem (a, x) pairs, fp16-rounded identically to gmem values
                buf[tloc * 16 + cloc]     = __floats2half2_rn(av0, xs0);
                buf[tloc * 16 + cloc + 1] = __floats2half2_rn(av1, xs1);
            }
    __syncwarp();

    // ---- fused chunk-summary scan: 2 lanes per column, 32 t each ----
    {
        int col = lane >> 1;           // 0..15
        int tp  = lane & 1;            // half selector
        int t0  = tp * 32;
        float A = 1.f, X = 0.f;
        #pragma unroll 8
        for (int t = 0; t < 32; t++) {
            float2 ax = __half22float2(buf[(t0 + t) * 16 + col]);
            X = fmaf(ax.x, X, ax.y);
            A *= ax.x;
        }
        float A1 = __shfl_xor_sync(0xffffffffu, A, 1);
        float X1 = __shfl_xor_sync(0xffffffffu, X, 1);
        if (tp == 0) {
            float Ac = A * A1;                    // A0 * A1
            float Xc = fmaf(A1, X, X1);           // A1*X0 + X1
            int row0 = mBase + wm * 64;           // chunk start token
            int b    = row0 >> 12;                // / S_LEN
            int cch  = (row0 & (S_LEN - 1)) >> 6; // / CHUNK
            int eb   = e * BATCH + b;
            int gcol = nBase + wn * 16 + col;
            g_sumAX[(eb * NCHUNK + cch) * D_MODEL + gcol] = make_float2(Ac, Xc);
        }
    }
}

// ---------------------------------------------------------------------------
// Serial prefix over chunks (MLP-4 prefetch)
// ---------------------------------------------------------------------------
__global__ __launch_bounds__(256) void scan_pass2() {
    int idx = blockIdx.x * 256 + threadIdx.x;
    int eb = idx >> 10, d = idx & 1023;
    const float2* s = g_sumAX + eb * NCHUNK * D_MODEL + d;
    float* hs = g_hstart + eb * NCHUNK * D_MODEL + d;
    float h = 0.f;
    #pragma unroll
    for (int c = 0; c < NCHUNK; c += 4) {
        float2 s0 = s[(c + 0) * D_MODEL];
        float2 s1 = s[(c + 1) * D_MODEL];
        float2 s2 = s[(c + 2) * D_MODEL];
        float2 s3 = s[(c + 3) * D_MODEL];
        hs[(c + 0) * D_MODEL] = h; h = fmaf(s0.x, h, s0.y);
        hs[(c + 1) * D_MODEL] = h; h = fmaf(s1.x, h, s1.y);
        hs[(c + 2) * D_MODEL] = h; h = fmaf(s2.x, h, s2.y);
        hs[(c + 3) * D_MODEL] = h; h = fmaf(s3.x, h, s3.y);
    }
}

// ---------------------------------------------------------------------------
// Re-scan each chunk with correct start state + router combine
// ---------------------------------------------------------------------------
__global__ __launch_bounds__(256) void scan_pass3(float* __restrict__ out) {
    int d2 = blockIdx.x * 256 + threadIdx.x;        // channel pair 0..511
    int c  = blockIdx.y;
    int b  = blockIdx.z;
    __shared__ float ws[CHUNK * NEXP];
    int t0 = c * CHUNK;
    ws[threadIdx.x] = g_w[(size_t)(b * S_LEN + t0) * NEXP + threadIdx.x];
    __syncthreads();

    float2 h[NEXP];
    size_t xbase[NEXP];
    #pragma unroll
    for (int e = 0; e < NEXP; e++) {
        int eb = e * BATCH + b;
        h[e] = *(const float2*)(g_hstart + (eb * NCHUNK + c) * D_MODEL + 2 * d2);
        xbase[e] = ((size_t)eb * S_LEN + t0) * D_MODEL + 2 * d2;
    }
    float* op = out + ((size_t)(b * S_LEN + t0)) * D_MODEL + 2 * d2;
    #pragma unroll 4
    for (int t = 0; t < CHUNK; t++) {
        float2 acc = make_float2(0.f, 0.f);
        #pragma unroll
        for (int e = 0; e < NEXP; e++) {
            size_t idx = xbase[e] + (size_t)t * D_MODEL;
            float2 a  = __half22float2(*(const __half2*)(g_a_h  + idx));
            float2 xv = __half22float2(*(const __half2*)(g_xs_h + idx));
            h[e].x = fmaf(a.x, h[e].x, xv.x);
            h[e].y = fmaf(a.y, h[e].y, xv.y);
            float w = ws[t * NEXP + e];
            acc.x = fmaf(w, h[e].x, acc.x);
            acc.y = fmaf(w, h[e].y, acc.y);
        }
        *(float2*)(op + (size_t)t * D_MODEL) = acc;
    }
}

// ---------------------------------------------------------------------------
// Launch
// ---------------------------------------------------------------------------
extern "C" void kernel_launch(void* const* d_in, const int* in_sizes, int n_in,
                              void* d_out, int out_size) {
    const float* x     = (const float*)d_in[0];
    const float* Wg    = (const float*)d_in[1];
    const float* bg    = (const float*)d_in[2];
    const float* Wv    = (const float*)d_in[3];
    const float* bv    = (const float*)d_in[4];
    const float* Wd    = (const float*)d_in[5];
    const float* bd    = (const float*)d_in[6];
    const float* Wgate = (const float*)d_in[7];
    float* out = (float*)d_out;

    cudaFuncSetAttribute(proj_gemm_kernel,
                         cudaFuncAttributeMaxDynamicSharedMemorySize, SMEM_BYTES);

    // W fp32->fp16 conversion; router converts x while computing gates
    f2h_w_kernel<<<(3 * NW4) / 256, 256>>>(
        (const float4*)Wg, (const float4*)Wv, (const float4*)Wd);
    router_kernel<<<(NTOK * 32) / 256, 256>>>(x, Wgate);

    proj_gemm_kernel<<<dim3(NTOK / BM, D_MODEL / BN, NEXP), 256, SMEM_BYTES>>>(bg, bv, bd);

    scan_pass2<<<(NEXP * BATCH * D_MODEL) / 256, 256>>>();
    scan_pass3<<<dim3(D_MODEL / 2 / 256, NCHUNK, BATCH), 256>>>(out);
}

// round 11
// speedup vs baseline: 4.4034x; 1.0025x over previous
#include <cuda_runtime.h>
#include <cuda_fp16.h>
#include <cstdint>
#include <math.h>

// ---------------------------------------------------------------------------
// Problem constants
// ---------------------------------------------------------------------------
#define D_MODEL 1024
#define S_LEN   4096
#define BATCH   4
#define NEXP    4
#define NTOK    16384
#define CHUNK   64
#define NCHUNK  64

// GEMM tiling (fp16 mma.m16n8k16), 512-thread CTA
#define BM 256
#define BN 64
#define BKH 64                      // K halves per stage (=128 bytes/row)
#define NKB (D_MODEL / BKH)         // 16 stages
#define PITCH 144                   // bytes per smem row (128B data + 16B pad)
#define AROWS BM                    // 256
#define BROWS (3 * BN)              // 192
#define STG_ROWS (AROWS + BROWS)    // 448
#define STG_BYTES (STG_ROWS * PITCH)        // 64512
#define SMEM_BYTES (2 * STG_BYTES)          // 129024

// ---------------------------------------------------------------------------
// Scratch (device globals; no dynamic allocation allowed)
// ---------------------------------------------------------------------------
__device__ __half g_xs_h[(size_t)NEXP * NTOK * D_MODEL];         // fp16 sigmoid(g)*tanh(v)
__device__ __half g_a_h [(size_t)NEXP * NTOK * D_MODEL];         // fp16 decay a
__device__ float2 g_sumAX[NEXP * BATCH * NCHUNK * D_MODEL];      // per-chunk (prodA, scanX)
__device__ float  g_hstart[NEXP * BATCH * NCHUNK * D_MODEL];
__device__ float  g_w[NTOK * NEXP];
__device__ __half g_xh[(size_t)NTOK * D_MODEL];                  // fp16 x
__device__ __half g_wh[(size_t)3 * NEXP * D_MODEL * D_MODEL];    // fp16 W (mat-major)

// ---------------------------------------------------------------------------
// Helpers
// ---------------------------------------------------------------------------
// exp2 on FMA/ALU pipes only (no MUFU): rel err ~1e-6
__device__ __forceinline__ float exp2_fma(float t) {
    float r  = t + 12582912.0f;              // round-to-int (2^23 * 1.5)
    int   ir = __float_as_int(r);
    float f  = t - (r - 12582912.0f);        // f in [-0.5, 0.5]
    float p  = 1.3333558146e-3f;
    p = fmaf(p, f, 9.6180886130e-3f);
    p = fmaf(p, f, 5.5504108664e-2f);
    p = fmaf(p, f, 2.4022650696e-1f);
    p = fmaf(p, f, 6.9314718056e-1f);
    p = fmaf(p, f, 1.0f);
    float s = __int_as_float((ir << 23) + 0x3F800000);
    return s * p;
}
__device__ __forceinline__ float frcp_(float x) {
    float y = __uint_as_float(0x7EF311C3u - __float_as_uint(x));
    y = y * (2.0f - x * y);
    y = y * (2.0f - x * y);
    y = y * (2.0f - x * y);
    return y;
}
__device__ __forceinline__ float sigmoid_acc(float z) {
    z = fminf(fmaxf(z, -30.0f), 30.0f);
    return frcp_(1.0f + exp2_fma(-1.4426950408889634f * z));
}
__device__ __forceinline__ float tanh_acc(float v) {
    v = fminf(fmaxf(v, -9.0f), 9.0f);
    float t = exp2_fma(2.8853900817779268f * v);
    return (t - 1.0f) * frcp_(t + 1.0f);
}

__device__ __forceinline__ void mma_f16(float* c, const uint32_t* a, const uint32_t* b) {
    asm volatile(
        "mma.sync.aligned.m16n8k16.row.col.f32.f16.f16.f32 "
        "{%0,%1,%2,%3}, {%4,%5,%6,%7}, {%8,%9}, {%0,%1,%2,%3};\n"
        : "+f"(c[0]), "+f"(c[1]), "+f"(c[2]), "+f"(c[3])
        : "r"(a[0]), "r"(a[1]), "r"(a[2]), "r"(a[3]), "r"(b[0]), "r"(b[1]));
}

__device__ __forceinline__ void ldsm4(uint32_t* r, uint32_t addr) {
    asm volatile(
        "ldmatrix.sync.aligned.m8n8.x4.shared.b16 {%0,%1,%2,%3}, [%4];"
        : "=r"(r[0]), "=r"(r[1]), "=r"(r[2]), "=r"(r[3]) : "r"(addr));
}

__device__ __forceinline__ void cpasync16(uint32_t dst_smem, const void* src) {
    asm volatile("cp.async.cg.shared.global [%0], [%1], 16;" :: "r"(dst_smem), "l"(src));
}
__device__ __forceinline__ void cp_commit() { asm volatile("cp.async.commit_group;"); }
template <int N>
__device__ __forceinline__ void cp_wait() { asm volatile("cp.async.wait_group %0;" :: "n"(N)); }

// ---------------------------------------------------------------------------
// Merged pre-pass: router (blocks [0, NTOK/8)) + W fp32->fp16 (rest).
// Router also converts x -> fp16 while it has the data.
// ---------------------------------------------------------------------------
#define NW4 ((NEXP * D_MODEL * D_MODEL) / 4)
#define ROUTER_BLOCKS (NTOK / 8)            // 2048: 8 tokens (warps) per block
#define CONV_BLOCKS ((3 * NW4) / 512)       // 6144: 2 float4 per thread
#define PRE_BLOCKS (ROUTER_BLOCKS + CONV_BLOCKS)

__device__ __forceinline__ void conv_one(int j, const float4* Wg, const float4* Wv,
                                         const float4* Wd) {
    const float4* src;
    __half2* dst;
    int off;
    if (j < NW4) {
        src = Wg;  dst = (__half2*)g_wh;               off = j;
    } else if (j < 2 * NW4) {
        src = Wv;  dst = (__half2*)g_wh + 2 * NW4;     off = j - NW4;
    } else {
        src = Wd;  dst = (__half2*)g_wh + 4 * NW4;     off = j - 2 * NW4;
    }
    float4 v = src[off];
    dst[2 * off]     = __floats2half2_rn(v.x, v.y);
    dst[2 * off + 1] = __floats2half2_rn(v.z, v.w);
}

__global__ __launch_bounds__(256) void prepass_kernel(
    const float* __restrict__ x, const float* __restrict__ Wgate,
    const float4* __restrict__ Wg, const float4* __restrict__ Wv,
    const float4* __restrict__ Wd)
{
    if (blockIdx.x >= ROUTER_BLOCKS) {
        int j0 = (blockIdx.x - ROUTER_BLOCKS) * 512 + threadIdx.x;
        conv_one(j0, Wg, Wv, Wd);
        conv_one(j0 + 256, Wg, Wv, Wd);
        return;
    }
    // ---- router part: one warp per token ----
    int gtid  = blockIdx.x * 256 + threadIdx.x;
    int token = gtid >> 5;
    int lane  = gtid & 31;
    const float* xr = x + (size_t)token * D_MODEL;
    __half* xo = g_xh + (size_t)token * D_MODEL;

    float a0 = 0.f, a1 = 0.f, a2 = 0.f, a3 = 0.f;
    #pragma unroll 8
    for (int k = lane; k < D_MODEL; k += 32) {
        float xv = xr[k];
        xo[k] = __float2half_rn(xv);
        a0 = fmaf(xv, Wgate[k],               a0);
        a1 = fmaf(xv, Wgate[D_MODEL + k],     a1);
        a2 = fmaf(xv, Wgate[2 * D_MODEL + k], a2);
        a3 = fmaf(xv, Wgate[3 * D_MODEL + k], a3);
    }
    #pragma unroll
    for (int o = 16; o; o >>= 1) {
        a0 += __shfl_down_sync(0xffffffffu, a0, o);
        a1 += __shfl_down_sync(0xffffffffu, a1, o);
        a2 += __shfl_down_sync(0xffffffffu, a2, o);
        a3 += __shfl_down_sync(0xffffffffu, a3, o);
    }
    if (lane == 0) {
        float l[4] = {a0, a1, a2, a3};
        int i0 = 0;
        #pragma unroll
        for (int i = 1; i < 4; i++) if (l[i] > l[i0]) i0 = i;
        int i1 = -1;
        #pragma unroll
        for (int i = 0; i < 4; i++) if (i != i0 && (i1 < 0 || l[i] > l[i1])) i1 = i;
        float ex = __expf(l[i1] - l[i0]);
        float den = 1.0f + ex;
        float wv[4] = {0.f, 0.f, 0.f, 0.f};
        wv[i0] = 1.0f / den;
        wv[i1] = ex / den;
        *(float4*)(g_w + (size_t)token * NEXP) = make_float4(wv[0], wv[1], wv[2], wv[3]);
    }
}

// ---------------------------------------------------------------------------
// Fused projection GEMM: fp16 mma.m16n8k16 + ldmatrix, 2-stage cp.async.
// CTA 256(M) x 64(N) x 3 matrices, 512 threads. 16 warps = 4(M) x 4(N),
// warp tile 64x16. Epilogue: activations -> fp16 xs/a + fused chunk-summary
// scan (warp m-tile = 64 tokens = exactly one scan chunk).
// ---------------------------------------------------------------------------
__global__ __launch_bounds__(512, 1) void proj_gemm_kernel(
    const float* __restrict__ bg, const float* __restrict__ bv,
    const float* __restrict__ bd)
{
    extern __shared__ char smem[];
    const uint32_t sbase = (uint32_t)__cvta_generic_to_shared(smem);

    const int e     = blockIdx.z;
    const int mBase = blockIdx.x * BM;
    const int nBase = blockIdx.y * BN;

    const int tid  = threadIdx.x;
    const int wid  = tid >> 5, lane = tid & 31;
    const int wm   = wid >> 2, wn = wid & 3;   // 4(M) x 4(N)
    const int grp  = lane >> 2, qid = lane & 3;

    const __half* xh = g_xh;
    const __half* wmat[3] = {
        g_wh + (size_t)0 * NEXP * D_MODEL * D_MODEL + (size_t)e * D_MODEL * D_MODEL,
        g_wh + (size_t)1 * NEXP * D_MODEL * D_MODEL + (size_t)e * D_MODEL * D_MODEL,
        g_wh + (size_t)2 * NEXP * D_MODEL * D_MODEL + (size_t)e * D_MODEL * D_MODEL };

    const int rA = wm * 64 + ((lane >> 3) & 1) * 8 + (lane & 7);
    const int kA = (lane >> 4) * 16;
    const int rB = wn * 16 + ((lane >> 4) & 1) * 8 + (lane & 7);
    const int kB = ((lane >> 3) & 1) * 16;

    const uint32_t addrA0 = sbase + (uint32_t)rA * PITCH + kA;
    const uint32_t addrB0 = sbase + (uint32_t)(AROWS + rB) * PITCH + kB;

    float acc[3][4][2][4];
    #pragma unroll
    for (int m = 0; m < 3; m++)
        #pragma unroll
        for (int i = 0; i < 4; i++)
            #pragma unroll
            for (int j = 0; j < 2; j++)
                #pragma unroll
                for (int r = 0; r < 4; r++) acc[m][i][j][r] = 0.f;

    // producer: 448 rows x 8 chunks = 3584 chunks per stage, 7 per thread
    auto load_stage = [&](int kb, int st) {
        const uint32_t dst0 = sbase + st * STG_BYTES;
        const int kcol = kb * BKH;
        #pragma unroll
        for (int it = 0; it < 7; it++) {
            int cid = tid + it * 512;
            int row = cid >> 3, c = cid & 7;
            const __half* src;
            if (row < AROWS) {
                src = xh + (size_t)(mBase + row) * D_MODEL + kcol + c * 8;
            } else {
                int r2 = row - AROWS;
                src = wmat[r2 >> 6] + (size_t)(nBase + (r2 & 63)) * D_MODEL + kcol + c * 8;
            }
            cpasync16(dst0 + (uint32_t)row * PITCH + c * 16, src);
        }
    };

    load_stage(0, 0);
    cp_commit();

    for (int kb = 0; kb < NKB; kb++) {
        if (kb + 1 < NKB) {
            load_stage(kb + 1, (kb + 1) & 1);
            cp_commit();
            cp_wait<1>();
        } else {
            cp_wait<0>();
        }
        __syncthreads();

        const uint32_t stoff = (kb & 1) * STG_BYTES;
        const uint32_t aA = addrA0 + stoff;
        const uint32_t aB = addrB0 + stoff;

        #pragma unroll
        for (int s = 0; s < 4; s++) {
            uint32_t af[4][4];
            #pragma unroll
            for (int i = 0; i < 4; i++)
                ldsm4(af[i], aA + i * (16 * PITCH) + s * 32);
            #pragma unroll
            for (int m = 0; m < 3; m++) {
                uint32_t bf[4];
                ldsm4(bf, aB + m * (64 * PITCH) + s * 32);
                #pragma unroll
                for (int j = 0; j < 2; j++)
                    #pragma unroll
                    for (int i = 0; i < 4; i++)
                        mma_f16(acc[m][i][j], af[i], bf + 2 * j);
            }
        }
        __syncthreads();
    }
    // Stage smem is dead after the final barrier -> per-warp scan buffer.
    // 16 warps x 4 KB = 64 KB <= 126 KB total smem.
    __half2* buf = (__half2*)(smem + wid * 4096);

    // ---- fused epilogue: activations -> fp16 xs/a (gmem) + smem (a,x) tile ----
    const float* bias0 = bg + e * D_MODEL;
    const float* bias1 = bv + e * D_MODEL;
    const float* bias2 = bd + e * D_MODEL;
    #pragma unroll
    for (int i = 0; i < 4; i++)
        #pragma unroll
        for (int j = 0; j < 2; j++)
            #pragma unroll
            for (int h = 0; h < 2; h++) {
                int tloc = i * 16 + h * 8 + grp;             // 0..63 within chunk
                int cloc = j * 8 + qid * 2;                  // 0..14 within warp cols
                int row = mBase + wm * 64 + tloc;
                int col = nBase + wn * 16 + cloc;
                float g0 = acc[0][i][j][h * 2 + 0] + __ldg(bias0 + col);
                float g1 = acc[0][i][j][h * 2 + 1] + __ldg(bias0 + col + 1);
                float v0 = acc[1][i][j][h * 2 + 0] + __ldg(bias1 + col);
                float v1 = acc[1][i][j][h * 2 + 1] + __ldg(bias1 + col + 1);
                float d0 = acc[2][i][j][h * 2 + 0] + __ldg(bias2 + col);
                float d1 = acc[2][i][j][h * 2 + 1] + __ldg(bias2 + col + 1);
                float xs0 = sigmoid_acc(g0) * tanh_acc(v0);
                float xs1 = sigmoid_acc(g1) * tanh_acc(v1);
                float av0 = 0.001f + 0.998f * sigmoid_acc(d0);
                float av1 = 0.001f + 0.998f * sigmoid_acc(d1);
                __half2 xsh = __floats2half2_rn(xs0, xs1);
                __half2 avh = __floats2half2_rn(av0, av1);
                size_t base = ((size_t)e * NTOK + row) * D_MODEL + col;
                *(__half2*)(g_xs_h + base) = xsh;
                *(__half2*)(g_a_h  + base) = avh;
                buf[tloc * 16 + cloc]     = __floats2half2_rn(av0, xs0);
                buf[tloc * 16 + cloc + 1] = __floats2half2_rn(av1, xs1);
            }
    __syncwarp();

    // ---- fused chunk-summary scan: 2 lanes per column, 32 t each ----
    {
        int col = lane >> 1;           // 0..15
        int tp  = lane & 1;            // half selector
        int t0  = tp * 32;
        float A = 1.f, X = 0.f;
        #pragma unroll 8
        for (int t = 0; t < 32; t++) {
            float2 ax = __half22float2(buf[(t0 + t) * 16 + col]);
            X = fmaf(ax.x, X, ax.y);
            A *= ax.x;
        }
        float A1 = __shfl_xor_sync(0xffffffffu, A, 1);
        float X1 = __shfl_xor_sync(0xffffffffu, X, 1);
        if (tp == 0) {
            float Ac = A * A1;
            float Xc = fmaf(A1, X, X1);
            int row0 = mBase + wm * 64;           // chunk start token
            int b    = row0 >> 12;                // / S_LEN
            int cch  = (row0 & (S_LEN - 1)) >> 6; // / CHUNK
            int eb   = e * BATCH + b;
            int gcol = nBase + wn * 16 + col;
            g_sumAX[(eb * NCHUNK + cch) * D_MODEL + gcol] = make_float2(Ac, Xc);
        }
    }
}

// ---------------------------------------------------------------------------
// Serial prefix over chunks (MLP-8 prefetch)
// ---------------------------------------------------------------------------
__global__ __launch_bounds__(256) void scan_pass2() {
    int idx = blockIdx.x * 256 + threadIdx.x;
    int eb = idx >> 10, d = idx & 1023;
    const float2* s = g_sumAX + eb * NCHUNK * D_MODEL + d;
    float* hs = g_hstart + eb * NCHUNK * D_MODEL + d;
    float h = 0.f;
    #pragma unroll
    for (int c = 0; c < NCHUNK; c += 8) {
        float2 sv[8];
        #pragma unroll
        for (int u = 0; u < 8; u++) sv[u] = s[(c + u) * D_MODEL];
        #pragma unroll
        for (int u = 0; u < 8; u++) {
            hs[(c + u) * D_MODEL] = h;
            h = fmaf(sv[u].x, h, sv[u].y);
        }
    }
}

// ---------------------------------------------------------------------------
// Re-scan each chunk with correct start state + router combine
// ---------------------------------------------------------------------------
__global__ __launch_bounds__(256) void scan_pass3(float* __restrict__ out) {
    int d2 = blockIdx.x * 256 + threadIdx.x;        // channel pair 0..511
    int c  = blockIdx.y;
    int b  = blockIdx.z;
    __shared__ float ws[CHUNK * NEXP];
    int t0 = c * CHUNK;
    ws[threadIdx.x] = g_w[(size_t)(b * S_LEN + t0) * NEXP + threadIdx.x];
    __syncthreads();

    float2 h[NEXP];
    size_t xbase[NEXP];
    #pragma unroll
    for (int e = 0; e < NEXP; e++) {
        int eb = e * BATCH + b;
        h[e] = *(const float2*)(g_hstart + (eb * NCHUNK + c) * D_MODEL + 2 * d2);
        xbase[e] = ((size_t)eb * S_LEN + t0) * D_MODEL + 2 * d2;
    }
    float* op = out + ((size_t)(b * S_LEN + t0)) * D_MODEL + 2 * d2;
    #pragma unroll 4
    for (int t = 0; t < CHUNK; t++) {
        float2 acc = make_float2(0.f, 0.f);
        #pragma unroll
        for (int e = 0; e < NEXP; e++) {
            size_t idx = xbase[e] + (size_t)t * D_MODEL;
            float2 a  = __half22float2(*(const __half2*)(g_a_h  + idx));
            float2 xv = __half22float2(*(const __half2*)(g_xs_h + idx));
            h[e].x = fmaf(a.x, h[e].x, xv.x);
            h[e].y = fmaf(a.y, h[e].y, xv.y);
            float w = ws[t * NEXP + e];
            acc.x = fmaf(w, h[e].x, acc.x);
            acc.y = fmaf(w, h[e].y, acc.y);
        }
        *(float2*)(op + (size_t)t * D_MODEL) = acc;
    }
}

// ---------------------------------------------------------------------------
// Launch
// ---------------------------------------------------------------------------
extern "C" void kernel_launch(void* const* d_in, const int* in_sizes, int n_in,
                              void* d_out, int out_size) {
    const float* x     = (const float*)d_in[0];
    const float* Wg    = (const float*)d_in[1];
    const float* bg    = (const float*)d_in[2];
    const float* Wv    = (const float*)d_in[3];
    const float* bv    = (const float*)d_in[4];
    const float* Wd    = (const float*)d_in[5];
    const float* bd    = (const float*)d_in[6];
    const float* Wgate = (const float*)d_in[7];
    float* out = (float*)d_out;

    cudaFuncSetAttribute(proj_gemm_kernel,
                         cudaFuncAttributeMaxDynamicSharedMemorySize, SMEM_BYTES);

    // Merged router + W fp32->fp16 conversion
    prepass_kernel<<<PRE_BLOCKS, 256>>>(x, Wgate, (const float4*)Wg,
                                        (const float4*)Wv, (const float4*)Wd);

    proj_gemm_kernel<<<dim3(NTOK / BM, D_MODEL / BN, NEXP), 512, SMEM_BYTES>>>(bg, bv, bd);

    scan_pass2<<<(NEXP * BATCH * D_MODEL) / 256, 256>>>();
    scan_pass3<<<dim3(D_MODEL / 2 / 256, NCHUNK, BATCH), 256>>>(out);
}

// round 12
// speedup vs baseline: 4.8877x; 1.1100x over previous
#include <cuda_runtime.h>
#include <cuda_fp16.h>
#include <cstdint>
#include <math.h>

// ---------------------------------------------------------------------------
// Problem constants
// ---------------------------------------------------------------------------
#define D_MODEL 1024
#define S_LEN   4096
#define BATCH   4
#define NEXP    4
#define NTOK    16384
#define CHUNK   64
#define NCHUNK  64

// GEMM tiling (fp16 mma.m16n8k16), 512-thread CTA, 3-stage pipeline
#define BM 256
#define BN 64
#define BKH 64                      // K halves per stage (=128 bytes/row)
#define NKB (D_MODEL / BKH)         // 16 stages
#define PITCH 144                   // bytes per smem row (128B data + 16B pad)
#define AROWS BM                    // 256
#define BROWS (3 * BN)              // 192
#define STG_ROWS (AROWS + BROWS)    // 448
#define STG_BYTES (STG_ROWS * PITCH)        // 64512
#define NSTG 3
#define SMEM_BYTES (NSTG * STG_BYTES)       // 193536

// ---------------------------------------------------------------------------
// Scratch (device globals; no dynamic allocation allowed)
// ---------------------------------------------------------------------------
__device__ __half g_xs_h[(size_t)NEXP * NTOK * D_MODEL];         // fp16 sigmoid(g)*tanh(v)
__device__ __half g_a_h [(size_t)NEXP * NTOK * D_MODEL];         // fp16 decay a
__device__ float2 g_sumAX[NEXP * BATCH * NCHUNK * D_MODEL];      // per-chunk (prodA, scanX)
__device__ float  g_hstart[NEXP * BATCH * NCHUNK * D_MODEL];
__device__ float  g_w[NTOK * NEXP];
__device__ __half g_xh[(size_t)NTOK * D_MODEL];                  // fp16 x
__device__ __half g_wh[(size_t)3 * NEXP * D_MODEL * D_MODEL];    // fp16 W (mat-major)

// ---------------------------------------------------------------------------
// Helpers
// ---------------------------------------------------------------------------
// exp2 on FMA/ALU pipes only (no MUFU): rel err ~1e-6
__device__ __forceinline__ float exp2_fma(float t) {
    float r  = t + 12582912.0f;              // round-to-int (2^23 * 1.5)
    int   ir = __float_as_int(r);
    float f  = t - (r - 12582912.0f);        // f in [-0.5, 0.5]
    float p  = 1.3333558146e-3f;
    p = fmaf(p, f, 9.6180886130e-3f);
    p = fmaf(p, f, 5.5504108664e-2f);
    p = fmaf(p, f, 2.4022650696e-1f);
    p = fmaf(p, f, 6.9314718056e-1f);
    p = fmaf(p, f, 1.0f);
    float s = __int_as_float((ir << 23) + 0x3F800000);
    return s * p;
}
__device__ __forceinline__ float frcp_(float x) {
    float y = __uint_as_float(0x7EF311C3u - __float_as_uint(x));
    y = y * (2.0f - x * y);
    y = y * (2.0f - x * y);
    y = y * (2.0f - x * y);
    return y;
}
__device__ __forceinline__ float sigmoid_acc(float z) {
    z = fminf(fmaxf(z, -30.0f), 30.0f);
    return frcp_(1.0f + exp2_fma(-1.4426950408889634f * z));
}
__device__ __forceinline__ float tanh_acc(float v) {
    v = fminf(fmaxf(v, -9.0f), 9.0f);
    float t = exp2_fma(2.8853900817779268f * v);
    return (t - 1.0f) * frcp_(t + 1.0f);
}

__device__ __forceinline__ void mma_f16(float* c, const uint32_t* a, const uint32_t* b) {
    asm volatile(
        "mma.sync.aligned.m16n8k16.row.col.f32.f16.f16.f32 "
        "{%0,%1,%2,%3}, {%4,%5,%6,%7}, {%8,%9}, {%0,%1,%2,%3};\n"
        : "+f"(c[0]), "+f"(c[1]), "+f"(c[2]), "+f"(c[3])
        : "r"(a[0]), "r"(a[1]), "r"(a[2]), "r"(a[3]), "r"(b[0]), "r"(b[1]));
}

__device__ __forceinline__ void ldsm4(uint32_t* r, uint32_t addr) {
    asm volatile(
        "ldmatrix.sync.aligned.m8n8.x4.shared.b16 {%0,%1,%2,%3}, [%4];"
        : "=r"(r[0]), "=r"(r[1]), "=r"(r[2]), "=r"(r[3]) : "r"(addr));
}

__device__ __forceinline__ void cpasync16(uint32_t dst_smem, const void* src) {
    asm volatile("cp.async.cg.shared.global [%0], [%1], 16;" :: "r"(dst_smem), "l"(src));
}
__device__ __forceinline__ void cp_commit() { asm volatile("cp.async.commit_group;"); }
template <int N>
__device__ __forceinline__ void cp_wait() { asm volatile("cp.async.wait_group %0;" :: "n"(N)); }

// ---------------------------------------------------------------------------
// Merged pre-pass: router (blocks [0, NTOK/8)) + W fp32->fp16 (rest).
// Router also converts x -> fp16 while it has the data.
// ---------------------------------------------------------------------------
#define NW4 ((NEXP * D_MODEL * D_MODEL) / 4)
#define ROUTER_BLOCKS (NTOK / 8)            // 2048: 8 tokens (warps) per block
#define CONV_BLOCKS ((3 * NW4) / 512)       // 6144: 2 float4 per thread
#define PRE_BLOCKS (ROUTER_BLOCKS + CONV_BLOCKS)

__device__ __forceinline__ void conv_one(int j, const float4* Wg, const float4* Wv,
                                         const float4* Wd) {
    const float4* src;
    __half2* dst;
    int off;
    if (j < NW4) {
        src = Wg;  dst = (__half2*)g_wh;               off = j;
    } else if (j < 2 * NW4) {
        src = Wv;  dst = (__half2*)g_wh + 2 * NW4;     off = j - NW4;
    } else {
        src = Wd;  dst = (__half2*)g_wh + 4 * NW4;     off = j - 2 * NW4;
    }
    float4 v = src[off];
    dst[2 * off]     = __floats2half2_rn(v.x, v.y);
    dst[2 * off + 1] = __floats2half2_rn(v.z, v.w);
}

__global__ __launch_bounds__(256) void prepass_kernel(
    const float* __restrict__ x, const float* __restrict__ Wgate,
    const float4* __restrict__ Wg, const float4* __restrict__ Wv,
    const float4* __restrict__ Wd)
{
    if (blockIdx.x >= ROUTER_BLOCKS) {
        int j0 = (blockIdx.x - ROUTER_BLOCKS) * 512 + threadIdx.x;
        conv_one(j0, Wg, Wv, Wd);
        conv_one(j0 + 256, Wg, Wv, Wd);
        return;
    }
    // ---- router part: one warp per token ----
    int gtid  = blockIdx.x * 256 + threadIdx.x;
    int token = gtid >> 5;
    int lane  = gtid & 31;
    const float* xr = x + (size_t)token * D_MODEL;
    __half* xo = g_xh + (size_t)token * D_MODEL;

    float a0 = 0.f, a1 = 0.f, a2 = 0.f, a3 = 0.f;
    #pragma unroll 8
    for (int k = lane; k < D_MODEL; k += 32) {
        float xv = xr[k];
        xo[k] = __float2half_rn(xv);
        a0 = fmaf(xv, Wgate[k],               a0);
        a1 = fmaf(xv, Wgate[D_MODEL + k],     a1);
        a2 = fmaf(xv, Wgate[2 * D_MODEL + k], a2);
        a3 = fmaf(xv, Wgate[3 * D_MODEL + k], a3);
    }
    #pragma unroll
    for (int o = 16; o; o >>= 1) {
        a0 += __shfl_down_sync(0xffffffffu, a0, o);
        a1 += __shfl_down_sync(0xffffffffu, a1, o);
        a2 += __shfl_down_sync(0xffffffffu, a2, o);
        a3 += __shfl_down_sync(0xffffffffu, a3, o);
    }
    if (lane == 0) {
        float l[4] = {a0, a1, a2, a3};
        int i0 = 0;
        #pragma unroll
        for (int i = 1; i < 4; i++) if (l[i] > l[i0]) i0 = i;
        int i1 = -1;
        #pragma unroll
        for (int i = 0; i < 4; i++) if (i != i0 && (i1 < 0 || l[i] > l[i1])) i1 = i;
        float ex = __expf(l[i1] - l[i0]);
        float den = 1.0f + ex;
        float wv[4] = {0.f, 0.f, 0.f, 0.f};
        wv[i0] = 1.0f / den;
        wv[i1] = ex / den;
        *(float4*)(g_w + (size_t)token * NEXP) = make_float4(wv[0], wv[1], wv[2], wv[3]);
    }
}

// ---------------------------------------------------------------------------
// Fused projection GEMM: fp16 mma.m16n8k16 + ldmatrix, 3-stage cp.async
// pipeline with single __syncthreads per stage (load issued 2 stages ahead,
// after the barrier -> race-free buffer reuse at distance 3).
// CTA 256(M) x 64(N) x 3 matrices, 512 threads. 16 warps = 4(M) x 4(N).
// Epilogue: activations -> fp16 xs/a + fused chunk-summary scan.
// ---------------------------------------------------------------------------
__global__ __launch_bounds__(512, 1) void proj_gemm_kernel(
    const float* __restrict__ bg, const float* __restrict__ bv,
    const float* __restrict__ bd)
{
    extern __shared__ char smem[];
    const uint32_t sbase = (uint32_t)__cvta_generic_to_shared(smem);

    const int e     = blockIdx.z;
    const int mBase = blockIdx.x * BM;
    const int nBase = blockIdx.y * BN;

    const int tid  = threadIdx.x;
    const int wid  = tid >> 5, lane = tid & 31;
    const int wm   = wid >> 2, wn = wid & 3;   // 4(M) x 4(N)
    const int grp  = lane >> 2, qid = lane & 3;

    const __half* xh = g_xh;
    const __half* wmat[3] = {
        g_wh + (size_t)0 * NEXP * D_MODEL * D_MODEL + (size_t)e * D_MODEL * D_MODEL,
        g_wh + (size_t)1 * NEXP * D_MODEL * D_MODEL + (size_t)e * D_MODEL * D_MODEL,
        g_wh + (size_t)2 * NEXP * D_MODEL * D_MODEL + (size_t)e * D_MODEL * D_MODEL };

    const int rA = wm * 64 + ((lane >> 3) & 1) * 8 + (lane & 7);
    const int kA = (lane >> 4) * 16;
    const int rB = wn * 16 + ((lane >> 4) & 1) * 8 + (lane & 7);
    const int kB = ((lane >> 3) & 1) * 16;

    const uint32_t addrA0 = sbase + (uint32_t)rA * PITCH + kA;
    const uint32_t addrB0 = sbase + (uint32_t)(AROWS + rB) * PITCH + kB;

    float acc[3][4][2][4];
    #pragma unroll
    for (int m = 0; m < 3; m++)
        #pragma unroll
        for (int i = 0; i < 4; i++)
            #pragma unroll
            for (int j = 0; j < 2; j++)
                #pragma unroll
                for (int r = 0; r < 4; r++) acc[m][i][j][r] = 0.f;

    // producer: 448 rows x 8 chunks = 3584 chunks per stage, 7 per thread
    auto load_stage = [&](int kb, int st) {
        const uint32_t dst0 = sbase + st * STG_BYTES;
        const int kcol = kb * BKH;
        #pragma unroll
        for (int it = 0; it < 7; it++) {
            int cid = tid + it * 512;
            int row = cid >> 3, c = cid & 7;
            const __half* src;
            if (row < AROWS) {
                src = xh + (size_t)(mBase + row) * D_MODEL + kcol + c * 8;
            } else {
                int r2 = row - AROWS;
                src = wmat[r2 >> 6] + (size_t)(nBase + (r2 & 63)) * D_MODEL + kcol + c * 8;
            }
            cpasync16(dst0 + (uint32_t)row * PITCH + c * 16, src);
        }
    };

    load_stage(0, 0);
    cp_commit();
    load_stage(1, 1);
    cp_commit();

    int st = 0;                      // stage buffer index = kb % 3
    for (int kb = 0; kb < NKB; kb++) {
        if (kb < NKB - 1) cp_wait<1>(); else cp_wait<0>();
        __syncthreads();
        // Issue next-next load AFTER the barrier: its target buffer was last
        // read in compute(kb-1), which all warps finished before this barrier.
        if (kb + 2 < NKB) {
            int st2 = st + 2; if (st2 >= NSTG) st2 -= NSTG;
            load_stage(kb + 2, st2);
            cp_commit();
        }

        const uint32_t stoff = (uint32_t)st * STG_BYTES;
        const uint32_t aA = addrA0 + stoff;
        const uint32_t aB = addrB0 + stoff;

        #pragma unroll
        for (int s = 0; s < 4; s++) {
            uint32_t af[4][4];
            #pragma unroll
            for (int i = 0; i < 4; i++)
                ldsm4(af[i], aA + i * (16 * PITCH) + s * 32);
            #pragma unroll
            for (int m = 0; m < 3; m++) {
                uint32_t bf[4];
                ldsm4(bf, aB + m * (64 * PITCH) + s * 32);
                #pragma unroll
                for (int j = 0; j < 2; j++)
                    #pragma unroll
                    for (int i = 0; i < 4; i++)
                        mma_f16(acc[m][i][j], af[i], bf + 2 * j);
            }
        }
        if (++st == NSTG) st = 0;
    }
    // Protect stage-smem reuse by the epilogue scan buffer.
    __syncthreads();
    __half2* buf = (__half2*)(smem + wid * 4096);   // 16 warps x 4 KB = 64 KB

    // ---- fused epilogue: activations -> fp16 xs/a (gmem) + smem (a,x) tile ----
    const float* bias0 = bg + e * D_MODEL;
    const float* bias1 = bv + e * D_MODEL;
    const float* bias2 = bd + e * D_MODEL;
    #pragma unroll
    for (int i = 0; i < 4; i++)
        #pragma unroll
        for (int j = 0; j < 2; j++)
            #pragma unroll
            for (int h = 0; h < 2; h++) {
                int tloc = i * 16 + h * 8 + grp;             // 0..63 within chunk
                int cloc = j * 8 + qid * 2;                  // 0..14 within warp cols
                int row = mBase + wm * 64 + tloc;
                int col = nBase + wn * 16 + cloc;
                float g0 = acc[0][i][j][h * 2 + 0] + __ldg(bias0 + col);
                float g1 = acc[0][i][j][h * 2 + 1] + __ldg(bias0 + col + 1);
                float v0 = acc[1][i][j][h * 2 + 0] + __ldg(bias1 + col);
                float v1 = acc[1][i][j][h * 2 + 1] + __ldg(bias1 + col + 1);
                float d0 = acc[2][i][j][h * 2 + 0] + __ldg(bias2 + col);
                float d1 = acc[2][i][j][h * 2 + 1] + __ldg(bias2 + col + 1);
                float xs0 = sigmoid_acc(g0) * tanh_acc(v0);
                float xs1 = sigmoid_acc(g1) * tanh_acc(v1);
                float av0 = 0.001f + 0.998f * sigmoid_acc(d0);
                float av1 = 0.001f + 0.998f * sigmoid_acc(d1);
                __half2 xsh = __floats2half2_rn(xs0, xs1);
                __half2 avh = __floats2half2_rn(av0, av1);
                size_t base = ((size_t)e * NTOK + row) * D_MODEL + col;
                *(__half2*)(g_xs_h + base) = xsh;
                *(__half2*)(g_a_h  + base) = avh;
                buf[tloc * 16 + cloc]     = __floats2half2_rn(av0, xs0);
                buf[tloc * 16 + cloc + 1] = __floats2half2_rn(av1, xs1);
            }
    __syncwarp();

    // ---- fused chunk-summary scan: 2 lanes per column, 32 t each ----
    {
        int col = lane >> 1;           // 0..15
        int tp  = lane & 1;            // half selector
        int t0  = tp * 32;
        float A = 1.f, X = 0.f;
        #pragma unroll 8
        for (int t = 0; t < 32; t++) {
            float2 ax = __half22float2(buf[(t0 + t) * 16 + col]);
            X = fmaf(ax.x, X, ax.y);
            A *= ax.x;
        }
        float A1 = __shfl_xor_sync(0xffffffffu, A, 1);
        float X1 = __shfl_xor_sync(0xffffffffu, X, 1);
        if (tp == 0) {
            float Ac = A * A1;
            float Xc = fmaf(A1, X, X1);
            int row0 = mBase + wm * 64;           // chunk start token
            int b    = row0 >> 12;                // / S_LEN
            int cch  = (row0 & (S_LEN - 1)) >> 6; // / CHUNK
            int eb   = e * BATCH + b;
            int gcol = nBase + wn * 16 + col;
            g_sumAX[(eb * NCHUNK + cch) * D_MODEL + gcol] = make_float2(Ac, Xc);
        }
    }
}

// ---------------------------------------------------------------------------
// Serial prefix over chunks (MLP-8 prefetch)
// ---------------------------------------------------------------------------
__global__ __launch_bounds__(256) void scan_pass2() {
    int idx = blockIdx.x * 256 + threadIdx.x;
    int eb = idx >> 10, d = idx & 1023;
    const float2* s = g_sumAX + eb * NCHUNK * D_MODEL + d;
    float* hs = g_hstart + eb * NCHUNK * D_MODEL + d;
    float h = 0.f;
    #pragma unroll
    for (int c = 0; c < NCHUNK; c += 8) {
        float2 sv[8];
        #pragma unroll
        for (int u = 0; u < 8; u++) sv[u] = s[(c + u) * D_MODEL];
        #pragma unroll
        for (int u = 0; u < 8; u++) {
            hs[(c + u) * D_MODEL] = h;
            h = fmaf(sv[u].x, h, sv[u].y);
        }
    }
}

// ---------------------------------------------------------------------------
// Re-scan each chunk with correct start state + router combine.
// 128-thread blocks, grid (4, NCHUNK, BATCH) = 1024 blocks for occupancy.
// ---------------------------------------------------------------------------
__global__ __launch_bounds__(128) void scan_pass3(float* __restrict__ out) {
    int d2 = blockIdx.x * 128 + threadIdx.x;        // channel pair 0..511
    int c  = blockIdx.y;
    int b  = blockIdx.z;
    __shared__ float ws[CHUNK * NEXP];
    int t0 = c * CHUNK;
    const float* wsrc = g_w + (size_t)(b * S_LEN + t0) * NEXP;
    ws[threadIdx.x]       = wsrc[threadIdx.x];
    ws[threadIdx.x + 128] = wsrc[threadIdx.x + 128];
    __syncthreads();

    float2 h[NEXP];
    size_t xbase[NEXP];
    #pragma unroll
    for (int e = 0; e < NEXP; e++) {
        int eb = e * BATCH + b;
        h[e] = *(const float2*)(g_hstart + (eb * NCHUNK + c) * D_MODEL + 2 * d2);
        xbase[e] = ((size_t)eb * S_LEN + t0) * D_MODEL + 2 * d2;
    }
    float* op = out + ((size_t)(b * S_LEN + t0)) * D_MODEL + 2 * d2;
    #pragma unroll 4
    for (int t = 0; t < CHUNK; t++) {
        float2 acc = make_float2(0.f, 0.f);
        #pragma unroll
        for (int e = 0; e < NEXP; e++) {
            size_t idx = xbase[e] + (size_t)t * D_MODEL;
            float2 a  = __half22float2(*(const __half2*)(g_a_h  + idx));
            float2 xv = __half22float2(*(const __half2*)(g_xs_h + idx));
            h[e].x = fmaf(a.x, h[e].x, xv.x);
            h[e].y = fmaf(a.y, h[e].y, xv.y);
            float w = ws[t * NEXP + e];
            acc.x = fmaf(w, h[e].x, acc.x);
            acc.y = fmaf(w, h[e].y, acc.y);
        }
        *(float2*)(op + (size_t)t * D_MODEL) = acc;
    }
}

// ---------------------------------------------------------------------------
// Launch
// ---------------------------------------------------------------------------
extern "C" void kernel_launch(void* const* d_in, const int* in_sizes, int n_in,
                              void* d_out, int out_size) {
    const float* x     = (const float*)d_in[0];
    const float* Wg    = (const float*)d_in[1];
    const float* bg    = (const float*)d_in[2];
    const float* Wv    = (const float*)d_in[3];
    const float* bv    = (const float*)d_in[4];
    const float* Wd    = (const float*)d_in[5];
    const float* bd    = (const float*)d_in[6];
    const float* Wgate = (const float*)d_in[7];
    float* out = (float*)d_out;

    cudaFuncSetAttribute(proj_gemm_kernel,
                         cudaFuncAttributeMaxDynamicSharedMemorySize, SMEM_BYTES);

    // Merged router + W fp32->fp16 conversion
    prepass_kernel<<<PRE_BLOCKS, 256>>>(x, Wgate, (const float4*)Wg,
                                        (const float4*)Wv, (const float4*)Wd);

    proj_gemm_kernel<<<dim3(NTOK / BM, D_MODEL / BN, NEXP), 512, SMEM_BYTES>>>(bg, bv, bd);

    scan_pass2<<<(NEXP * BATCH * D_MODEL) / 256, 256>>>();
    scan_pass3<<<dim3(D_MODEL / 2 / 128, NCHUNK, BATCH), 128>>>(out);
}

// round 15
// speedup vs baseline: 4.9366x; 1.0100x over previous
#include <cuda_runtime.h>
#include <cuda_fp16.h>
#include <cstdint>
#include <math.h>

// ---------------------------------------------------------------------------
// Problem constants
// ---------------------------------------------------------------------------
#define D_MODEL 1024
#define S_LEN   4096
#define BATCH   4
#define NEXP    4
#define NTOK    16384
#define CHUNK   64
#define NCHUNK  64

// GEMM tiling (fp16 mma.m16n8k16), 512-thread CTA, 3-stage pipeline
#define BM 256
#define BN 64
#define BKH 64                      // K halves per stage (=128 bytes/row)
#define NKB (D_MODEL / BKH)         // 16 stages
#define PITCH 144                   // bytes per smem row (128B data + 16B pad)
#define AROWS BM                    // 256
#define BROWS (3 * BN)              // 192
#define STG_ROWS (AROWS + BROWS)    // 448
#define STG_BYTES (STG_ROWS * PITCH)        // 64512
#define NSTG 3
#define SMEM_BYTES (NSTG * STG_BYTES)       // 193536

// ---------------------------------------------------------------------------
// Scratch (device globals; no dynamic allocation allowed)
// ---------------------------------------------------------------------------
// Interleaved per-channel-pair (a, x): .x = half2(a0,a1), .y = half2(x0,x1)
__device__ uint2  g_ax[(size_t)NEXP * NTOK * D_MODEL / 2];
__device__ float2 g_sumAX[NEXP * BATCH * NCHUNK * D_MODEL];      // per-chunk (prodA, scanX)
__device__ float  g_hstart[NEXP * BATCH * NCHUNK * D_MODEL];
__device__ float  g_w[NTOK * NEXP];
__device__ __half g_xh[(size_t)NTOK * D_MODEL];                  // fp16 x
__device__ __half g_wh[(size_t)3 * NEXP * D_MODEL * D_MODEL];    // fp16 W (mat-major)

// ---------------------------------------------------------------------------
// Helpers
// ---------------------------------------------------------------------------
// exp2 on FMA/ALU pipes only (no MUFU): rel err ~1e-6
__device__ __forceinline__ float exp2_fma(float t) {
    float r  = t + 12582912.0f;              // round-to-int (2^23 * 1.5)
    int   ir = __float_as_int(r);
    float f  = t - (r - 12582912.0f);        // f in [-0.5, 0.5]
    float p  = 1.3333558146e-3f;
    p = fmaf(p, f, 9.6180886130e-3f);
    p = fmaf(p, f, 5.5504108664e-2f);
    p = fmaf(p, f, 2.4022650696e-1f);
    p = fmaf(p, f, 6.9314718056e-1f);
    p = fmaf(p, f, 1.0f);
    float s = __int_as_float((ir << 23) + 0x3F800000);
    return s * p;
}
__device__ __forceinline__ float frcp_(float x) {
    float y = __uint_as_float(0x7EF311C3u - __float_as_uint(x));
    y = y * (2.0f - x * y);
    y = y * (2.0f - x * y);
    y = y * (2.0f - x * y);
    return y;
}
__device__ __forceinline__ float sigmoid_acc(float z) {
    z = fminf(fmaxf(z, -30.0f), 30.0f);
    return frcp_(1.0f + exp2_fma(-1.4426950408889634f * z));
}
__device__ __forceinline__ float tanh_acc(float v) {
    v = fminf(fmaxf(v, -9.0f), 9.0f);
    float t = exp2_fma(2.8853900817779268f * v);
    return (t - 1.0f) * frcp_(t + 1.0f);
}

__device__ __forceinline__ void mma_f16(float* c, const uint32_t* a, const uint32_t* b) {
    asm volatile(
        "mma.sync.aligned.m16n8k16.row.col.f32.f16.f16.f32 "
        "{%0,%1,%2,%3}, {%4,%5,%6,%7}, {%8,%9}, {%0,%1,%2,%3};\n"
        : "+f"(c[0]), "+f"(c[1]), "+f"(c[2]), "+f"(c[3])
        : "r"(a[0]), "r"(a[1]), "r"(a[2]), "r"(a[3]), "r"(b[0]), "r"(b[1]));
}

__device__ __forceinline__ void ldsm4(uint32_t* r, uint32_t addr) {
    asm volatile(
        "ldmatrix.sync.aligned.m8n8.x4.shared.b16 {%0,%1,%2,%3}, [%4];"
        : "=r"(r[0]), "=r"(r[1]), "=r"(r[2]), "=r"(r[3]) : "r"(addr));
}

__device__ __forceinline__ void cpasync16(uint32_t dst_smem, const void* src) {
    asm volatile("cp.async.cg.shared.global [%0], [%1], 16;" :: "r"(dst_smem), "l"(src));
}
__device__ __forceinline__ void cp_commit() { asm volatile("cp.async.commit_group;"); }
template <int N>
__device__ __forceinline__ void cp_wait() { asm volatile("cp.async.wait_group %0;" :: "n"(N)); }

// ---------------------------------------------------------------------------
// Merged pre-pass: router (blocks [0, NTOK/8)) + W fp32->fp16 (rest).
// Router also converts x -> fp16 (vectorized) while it has the data.
// ---------------------------------------------------------------------------
#define NW4 ((NEXP * D_MODEL * D_MODEL) / 4)
#define ROUTER_BLOCKS (NTOK / 8)            // 2048: 8 tokens (warps) per block
#define CONV_BLOCKS ((3 * NW4) / 512)       // 6144: 2 float4 per thread
#define PRE_BLOCKS (ROUTER_BLOCKS + CONV_BLOCKS)

__device__ __forceinline__ void conv_one(int j, const float4* Wg, const float4* Wv,
                                         const float4* Wd) {
    const float4* src;
    __half2* dst;
    int off;
    if (j < NW4) {
        src = Wg;  dst = (__half2*)g_wh;               off = j;
    } else if (j < 2 * NW4) {
        src = Wv;  dst = (__half2*)g_wh + 2 * NW4;     off = j - NW4;
    } else {
        src = Wd;  dst = (__half2*)g_wh + 4 * NW4;     off = j - 2 * NW4;
    }
    float4 v = src[off];
    dst[2 * off]     = __floats2half2_rn(v.x, v.y);
    dst[2 * off + 1] = __floats2half2_rn(v.z, v.w);
}

__global__ __launch_bounds__(256) void prepass_kernel(
    const float* __restrict__ x, const float* __restrict__ Wgate,
    const float4* __restrict__ Wg, const float4* __restrict__ Wv,
    const float4* __restrict__ Wd)
{
    if (blockIdx.x >= ROUTER_BLOCKS) {
        int j0 = (blockIdx.x - ROUTER_BLOCKS) * 512 + threadIdx.x;
        conv_one(j0, Wg, Wv, Wd);
        conv_one(j0 + 256, Wg, Wv, Wd);
        return;
    }
    // ---- router part: one warp per token, float4-vectorized ----
    int gtid  = blockIdx.x * 256 + threadIdx.x;
    int token = gtid >> 5;
    int lane  = gtid & 31;
    const float4* x4 = (const float4*)(x + (size_t)token * D_MODEL);
    __half2* xo2 = (__half2*)(g_xh + (size_t)token * D_MODEL);
    const float4* W0 = (const float4*)Wgate;
    const float4* W1 = (const float4*)(Wgate + D_MODEL);
    const float4* W2 = (const float4*)(Wgate + 2 * D_MODEL);
    const float4* W3 = (const float4*)(Wgate + 3 * D_MODEL);

    float a0 = 0.f, a1 = 0.f, a2 = 0.f, a3 = 0.f;
    #pragma unroll
    for (int k4 = lane; k4 < D_MODEL / 4; k4 += 32) {
        float4 xv = x4[k4];
        xo2[2 * k4]     = __floats2half2_rn(xv.x, xv.y);
        xo2[2 * k4 + 1] = __floats2half2_rn(xv.z, xv.w);
        float4 w;
        w = W0[k4];
        a0 = fmaf(xv.x, w.x, fmaf(xv.y, w.y, fmaf(xv.z, w.z, fmaf(xv.w, w.w, a0))));
        w = W1[k4];
        a1 = fmaf(xv.x, w.x, fmaf(xv.y, w.y, fmaf(xv.z, w.z, fmaf(xv.w, w.w, a1))));
        w = W2[k4];
        a2 = fmaf(xv.x, w.x, fmaf(xv.y, w.y, fmaf(xv.z, w.z, fmaf(xv.w, w.w, a2))));
        w = W3[k4];
        a3 = fmaf(xv.x, w.x, fmaf(xv.y, w.y, fmaf(xv.z, w.z, fmaf(xv.w, w.w, a3))));
    }
    #pragma unroll
    for (int o = 16; o; o >>= 1) {
        a0 += __shfl_down_sync(0xffffffffu, a0, o);
        a1 += __shfl_down_sync(0xffffffffu, a1, o);
        a2 += __shfl_down_sync(0xffffffffu, a2, o);
        a3 += __shfl_down_sync(0xffffffffu, a3, o);
    }
    if (lane == 0) {
        float l[4] = {a0, a1, a2, a3};
        int i0 = 0;
        #pragma unroll
        for (int i = 1; i < 4; i++) if (l[i] > l[i0]) i0 = i;
        int i1 = -1;
        #pragma unroll
        for (int i = 0; i < 4; i++) if (i != i0 && (i1 < 0 || l[i] > l[i1])) i1 = i;
        float ex = __expf(l[i1] - l[i0]);
        float den = 1.0f + ex;
        float wv[4] = {0.f, 0.f, 0.f, 0.f};
        wv[i0] = 1.0f / den;
        wv[i1] = ex / den;
        *(float4*)(g_w + (size_t)token * NEXP) = make_float4(wv[0], wv[1], wv[2], wv[3]);
    }
}

// ---------------------------------------------------------------------------
// Fused projection GEMM: fp16 mma.m16n8k16 + ldmatrix, 3-stage cp.async
// pipeline with single __syncthreads per stage (load issued 2 stages ahead).
// CTA 256(M) x 64(N) x 3 matrices, 512 threads. 16 warps = 4(M) x 4(N).
// Epilogue: activations -> interleaved (a,x) uint2 + fused chunk-summary scan.
// ---------------------------------------------------------------------------
__global__ __launch_bounds__(512, 1) void proj_gemm_kernel(
    const float* __restrict__ bg, const float* __restrict__ bv,
    const float* __restrict__ bd)
{
    extern __shared__ char smem[];
    const uint32_t sbase = (uint32_t)__cvta_generic_to_shared(smem);

    const int e     = blockIdx.z;
    const int mBase = blockIdx.x * BM;
    const int nBase = blockIdx.y * BN;

    const int tid  = threadIdx.x;
    const int wid  = tid >> 5, lane = tid & 31;
    const int wm   = wid >> 2, wn = wid & 3;   // 4(M) x 4(N)
    const int grp  = lane >> 2, qid = lane & 3;

    const __half* xh = g_xh;
    const __half* wmat[3] = {
        g_wh + (size_t)0 * NEXP * D_MODEL * D_MODEL + (size_t)e * D_MODEL * D_MODEL,
        g_wh + (size_t)1 * NEXP * D_MODEL * D_MODEL + (size_t)e * D_MODEL * D_MODEL,
        g_wh + (size_t)2 * NEXP * D_MODEL * D_MODEL + (size_t)e * D_MODEL * D_MODEL };

    const int rA = wm * 64 + ((lane >> 3) & 1) * 8 + (lane & 7);
    const int kA = (lane >> 4) * 16;
    const int rB = wn * 16 + ((lane >> 4) & 1) * 8 + (lane & 7);
    const int kB = ((lane >> 3) & 1) * 16;

    const uint32_t addrA0 = sbase + (uint32_t)rA * PITCH + kA;
    const uint32_t addrB0 = sbase + (uint32_t)(AROWS + rB) * PITCH + kB;

    float acc[3][4][2][4];
    #pragma unroll
    for (int m = 0; m < 3; m++)
        #pragma unroll
        for (int i = 0; i < 4; i++)
            #pragma unroll
            for (int j = 0; j < 2; j++)
                #pragma unroll
                for (int r = 0; r < 4; r++) acc[m][i][j][r] = 0.f;

    // producer: 448 rows x 8 chunks = 3584 chunks per stage, 7 per thread
    auto load_stage = [&](int kb, int st) {
        const uint32_t dst0 = sbase + st * STG_BYTES;
        const int kcol = kb * BKH;
        #pragma unroll
        for (int it = 0; it < 7; it++) {
            int cid = tid + it * 512;
            int row = cid >> 3, c = cid & 7;
            const __half* src;
            if (row < AROWS) {
                src = xh + (size_t)(mBase + row) * D_MODEL + kcol + c * 8;
            } else {
                int r2 = row - AROWS;
                src = wmat[r2 >> 6] + (size_t)(nBase + (r2 & 63)) * D_MODEL + kcol + c * 8;
            }
            cpasync16(dst0 + (uint32_t)row * PITCH + c * 16, src);
        }
    };

    load_stage(0, 0);
    cp_commit();
    load_stage(1, 1);
    cp_commit();

    int st = 0;                      // stage buffer index = kb % 3
    for (int kb = 0; kb < NKB; kb++) {
        if (kb < NKB - 1) cp_wait<1>(); else cp_wait<0>();
        __syncthreads();
        if (kb + 2 < NKB) {
            int st2 = st + 2; if (st2 >= NSTG) st2 -= NSTG;
            load_stage(kb + 2, st2);
            cp_commit();
        }

        const uint32_t stoff = (uint32_t)st * STG_BYTES;
        const uint32_t aA = addrA0 + stoff;
        const uint32_t aB = addrB0 + stoff;

        #pragma unroll
        for (int s = 0; s < 4; s++) {
            uint32_t af[4][4];
            #pragma unroll
            for (int i = 0; i < 4; i++)
                ldsm4(af[i], aA + i * (16 * PITCH) + s * 32);
            #pragma unroll
            for (int m = 0; m < 3; m++) {
                uint32_t bf[4];
                ldsm4(bf, aB + m * (64 * PITCH) + s * 32);
                #pragma unroll
                for (int j = 0; j < 2; j++)
                    #pragma unroll
                    for (int i = 0; i < 4; i++)
                        mma_f16(acc[m][i][j], af[i], bf + 2 * j);
            }
        }
        if (++st == NSTG) st = 0;
    }
    // Protect stage-smem reuse by the epilogue scan buffer.
    __syncthreads();
    __half2* buf = (__half2*)(smem + wid * 4096);   // 16 warps x 4 KB = 64 KB

    // ---- fused epilogue: activations -> interleaved (a,x) + smem tile ----
    const float* bias0 = bg + e * D_MODEL;
    const float* bias1 = bv + e * D_MODEL;
    const float* bias2 = bd + e * D_MODEL;
    #pragma unroll
    for (int i = 0; i < 4; i++)
        #pragma unroll
        for (int j = 0; j < 2; j++)
            #pragma unroll
            for (int h = 0; h < 2; h++) {
                int tloc = i * 16 + h * 8 + grp;             // 0..63 within chunk
                int cloc = j * 8 + qid * 2;                  // 0..14 within warp cols
                int row = mBase + wm * 64 + tloc;
                int col = nBase + wn * 16 + cloc;
                float g0 = acc[0][i][j][h * 2 + 0] + __ldg(bias0 + col);
                float g1 = acc[0][i][j][h * 2 + 1] + __ldg(bias0 + col + 1);
                float v0 = acc[1][i][j][h * 2 + 0] + __ldg(bias1 + col);
                float v1 = acc[1][i][j][h * 2 + 1] + __ldg(bias1 + col + 1);
                float d0 = acc[2][i][j][h * 2 + 0] + __ldg(bias2 + col);
                float d1 = acc[2][i][j][h * 2 + 1] + __ldg(bias2 + col + 1);
                float xs0 = sigmoid_acc(g0) * tanh_acc(v0);
                float xs1 = sigmoid_acc(g1) * tanh_acc(v1);
                float av0 = 0.001f + 0.998f * sigmoid_acc(d0);
                float av1 = 0.001f + 0.998f * sigmoid_acc(d1);
                __half2 xsh = __floats2half2_rn(xs0, xs1);
                __half2 avh = __floats2half2_rn(av0, av1);
                size_t base = ((size_t)e * NTOK + row) * D_MODEL + col;
                uint2 pr;
                pr.x = *reinterpret_cast<uint32_t*>(&avh);
                pr.y = *reinterpret_cast<uint32_t*>(&xsh);
                g_ax[base >> 1] = pr;
                buf[tloc * 16 + cloc]     = __floats2half2_rn(av0, xs0);
                buf[tloc * 16 + cloc + 1] = __floats2half2_rn(av1, xs1);
            }
    __syncwarp();

    // ---- fused chunk-summary scan: 2 lanes per column, 32 t each ----
    {
        int col = lane >> 1;           // 0..15
        int tp  = lane & 1;            // half selector
        int t0  = tp * 32;
        float A = 1.f, X = 0.f;
        #pragma unroll 8
        for (int t = 0; t < 32; t++) {
            float2 ax = __half22float2(buf[(t0 + t) * 16 + col]);
            X = fmaf(ax.x, X, ax.y);
            A *= ax.x;
        }
        float A1 = __shfl_xor_sync(0xffffffffu, A, 1);
        float X1 = __shfl_xor_sync(0xffffffffu, X, 1);
        if (tp == 0) {
            float Ac = A * A1;
            float Xc = fmaf(A1, X, X1);
            int row0 = mBase + wm * 64;           // chunk start token
            int b    = row0 >> 12;                // / S_LEN
            int cch  = (row0 & (S_LEN - 1)) >> 6; // / CHUNK
            int eb   = e * BATCH + b;
            int gcol = nBase + wn * 16 + col;
            g_sumAX[(eb * NCHUNK + cch) * D_MODEL + gcol] = make_float2(Ac, Xc);
        }
    }
}

// ---------------------------------------------------------------------------
// Serial prefix over chunks (MLP-8 prefetch)
// ---------------------------------------------------------------------------
__global__ __launch_bounds__(256) void scan_pass2() {
    int idx = blockIdx.x * 256 + threadIdx.x;
    int eb = idx >> 10, d = idx & 1023;
    const float2* s = g_sumAX + eb * NCHUNK * D_MODEL + d;
    float* hs = g_hstart + eb * NCHUNK * D_MODEL + d;
    float h = 0.f;
    #pragma unroll
    for (int c = 0; c < NCHUNK; c += 8) {
        float2 sv[8];
        #pragma unroll
        for (int u = 0; u < 8; u++) sv[u] = s[(c + u) * D_MODEL];
        #pragma unroll
        for (int u = 0; u < 8; u++) {
            hs[(c + u) * D_MODEL] = h;
            h = fmaf(sv[u].x, h, sv[u].y);
        }
    }
}

// ---------------------------------------------------------------------------
// Re-scan each chunk with correct start state + router combine.
// 4 channels per thread via uint4 loads of interleaved (a,x).
// ---------------------------------------------------------------------------
__global__ __launch_bounds__(128) void scan_pass3(float* __restrict__ out) {
    int d4 = blockIdx.x * 128 + threadIdx.x;        // channel quad 0..255
    int c  = blockIdx.y;
    int b  = blockIdx.z;
    __shared__ float ws[CHUNK * NEXP];
    int t0 = c * CHUNK;
    const float* wsrc = g_w + (size_t)(b * S_LEN + t0) * NEXP;
    ws[threadIdx.x]       = wsrc[threadIdx.x];
    ws[threadIdx.x + 128] = wsrc[threadIdx.x + 128];
    __syncthreads();

    float4 h[NEXP];
    const uint4* axp[NEXP];
    #pragma unroll
    for (int e = 0; e < NEXP; e++) {
        int eb = e * BATCH + b;
        h[e] = *(const float4*)(g_hstart + (eb * NCHUNK + c) * D_MODEL + 4 * d4);
        axp[e] = (const uint4*)g_ax + ((size_t)(eb * S_LEN + t0) * (D_MODEL / 4) + d4);
    }
    float* op = out + ((size_t)(b * S_LEN + t0)) * D_MODEL + 4 * d4;
    #pragma unroll 4
    for (int t = 0; t < CHUNK; t++) {
        float4 acc = make_float4(0.f, 0.f, 0.f, 0.f);
        #pragma unroll
        for (int e = 0; e < NEXP; e++) {
            uint4 v = axp[e][(size_t)t * (D_MODEL / 4)];
            float2 a01 = __half22float2(*reinterpret_cast<__half2*>(&v.x));
            float2 x01 = __half22float2(*reinterpret_cast<__half2*>(&v.y));
            float2 a23 = __half22float2(*reinterpret_cast<__half2*>(&v.z));
            float2 x23 = __half22float2(*reinterpret_cast<__half2*>(&v.w));
            h[e].x = fmaf(a01.x, h[e].x, x01.x);
            h[e].y = fmaf(a01.y, h[e].y, x01.y);
            h[e].z = fmaf(a23.x, h[e].z, x23.x);
            h[e].w = fmaf(a23.y, h[e].w, x23.y);
            float w = ws[t * NEXP + e];
            acc.x = fmaf(w, h[e].x, acc.x);
            acc.y = fmaf(w, h[e].y, acc.y);
            acc.z = fmaf(w, h[e].z, acc.z);
            acc.w = fmaf(w, h[e].w, acc.w);
        }
        *(float4*)(op + (size_t)t * D_MODEL) = acc;
    }
}

// ---------------------------------------------------------------------------
// Launch
// ---------------------------------------------------------------------------
extern "C" void kernel_launch(void* const* d_in, const int* in_sizes, int n_in,
                              void* d_out, int out_size) {
    const float* x     = (const float*)d_in[0];
    const float* Wg    = (const float*)d_in[1];
    const float* bg    = (const float*)d_in[2];
    const float* Wv    = (const float*)d_in[3];
    const float* bv    = (const float*)d_in[4];
    const float* Wd    = (const float*)d_in[5];
    const float* bd    = (const float*)d_in[6];
    const float* Wgate = (const float*)d_in[7];
    float* out = (float*)d_out;

    cudaFuncSetAttribute(proj_gemm_kernel,
                         cudaFuncAttributeMaxDynamicSharedMemorySize, SMEM_BYTES);

    // Merged router + W fp32->fp16 conversion
    prepass_kernel<<<PRE_BLOCKS, 256>>>(x, Wgate, (const float4*)Wg,
                                        (const float4*)Wv, (const float4*)Wd);

    proj_gemm_kernel<<<dim3(NTOK / BM, D_MODEL / BN, NEXP), 512, SMEM_BYTES>>>(bg, bv, bd);

    scan_pass2<<<(NEXP * BATCH * D_MODEL) / 256, 256>>>();
    scan_pass3<<<dim3(D_MODEL / 4 / 128, NCHUNK, BATCH), 128>>>(out);
}

// round 17
// speedup vs baseline: 4.9818x; 1.0092x over previous
#include <cuda_runtime.h>
#include <cuda_fp16.h>
#include <cstdint>
#include <math.h>

// ---------------------------------------------------------------------------
// Problem constants
// ---------------------------------------------------------------------------
#define D_MODEL 1024
#define S_LEN   4096
#define BATCH   4
#define NEXP    4
#define NTOK    16384
#define CHUNK2  32                  // scan sub-chunk (pass2/pass3 granularity)
#define NCHUNK2 128                 // S_LEN / CHUNK2

// GEMM tiling (fp16 mma.m16n8k16), 512-thread CTA, 3-stage pipeline
#define BM 256
#define BN 64
#define BKH 64                      // K halves per stage (=128 bytes/row)
#define NKB (D_MODEL / BKH)         // 16 stages
#define PITCH 144                   // bytes per smem row (128B data + 16B pad)
#define AROWS BM                    // 256
#define BROWS (3 * BN)              // 192
#define STG_ROWS (AROWS + BROWS)    // 448
#define STG_BYTES (STG_ROWS * PITCH)        // 64512
#define NSTG 3
#define SMEM_BYTES (NSTG * STG_BYTES)       // 193536

// ---------------------------------------------------------------------------
// Scratch (device globals; no dynamic allocation allowed)
// ---------------------------------------------------------------------------
// Interleaved per-channel-pair (a, x): .x = half2(a0,a1), .y = half2(x0,x1)
__device__ uint2  g_ax[(size_t)NEXP * NTOK * D_MODEL / 2];
__device__ float2 g_sumAX[NEXP * BATCH * NCHUNK2 * D_MODEL];     // per-32t (prodA, scanX)
__device__ float  g_hstart[NEXP * BATCH * NCHUNK2 * D_MODEL];
__device__ float  g_w[NTOK * NEXP];
__device__ __half g_xh[(size_t)NTOK * D_MODEL];                  // fp16 x
__device__ __half g_wh[(size_t)3 * NEXP * D_MODEL * D_MODEL];    // fp16 W (mat-major)

// ---------------------------------------------------------------------------
// Helpers
// ---------------------------------------------------------------------------
// exp2 on FMA/ALU pipes only (no MUFU): rel err ~1e-6
__device__ __forceinline__ float exp2_fma(float t) {
    float r  = t + 12582912.0f;              // round-to-int (2^23 * 1.5)
    int   ir = __float_as_int(r);
    float f  = t - (r - 12582912.0f);        // f in [-0.5, 0.5]
    float p  = 1.3333558146e-3f;
    p = fmaf(p, f, 9.6180886130e-3f);
    p = fmaf(p, f, 5.5504108664e-2f);
    p = fmaf(p, f, 2.4022650696e-1f);
    p = fmaf(p, f, 6.9314718056e-1f);
    p = fmaf(p, f, 1.0f);
    float s = __int_as_float((ir << 23) + 0x3F800000);
    return s * p;
}
__device__ __forceinline__ float frcp_(float x) {
    float y = __uint_as_float(0x7EF311C3u - __float_as_uint(x));
    y = y * (2.0f - x * y);
    y = y * (2.0f - x * y);
    y = y * (2.0f - x * y);
    return y;
}
__device__ __forceinline__ float sigmoid_acc(float z) {
    z = fminf(fmaxf(z, -30.0f), 30.0f);
    return frcp_(1.0f + exp2_fma(-1.4426950408889634f * z));
}
__device__ __forceinline__ float tanh_acc(float v) {
    v = fminf(fmaxf(v, -9.0f), 9.0f);
    float t = exp2_fma(2.8853900817779268f * v);
    return (t - 1.0f) * frcp_(t + 1.0f);
}

__device__ __forceinline__ void mma_f16(float* c, const uint32_t* a, const uint32_t* b) {
    asm volatile(
        "mma.sync.aligned.m16n8k16.row.col.f32.f16.f16.f32 "
        "{%0,%1,%2,%3}, {%4,%5,%6,%7}, {%8,%9}, {%0,%1,%2,%3};\n"
        : "+f"(c[0]), "+f"(c[1]), "+f"(c[2]), "+f"(c[3])
        : "r"(a[0]), "r"(a[1]), "r"(a[2]), "r"(a[3]), "r"(b[0]), "r"(b[1]));
}

__device__ __forceinline__ void ldsm4(uint32_t* r, uint32_t addr) {
    asm volatile(
        "ldmatrix.sync.aligned.m8n8.x4.shared.b16 {%0,%1,%2,%3}, [%4];"
        : "=r"(r[0]), "=r"(r[1]), "=r"(r[2]), "=r"(r[3]) : "r"(addr));
}

__device__ __forceinline__ void cpasync16(uint32_t dst_smem, const void* src) {
    asm volatile("cp.async.cg.shared.global [%0], [%1], 16;" :: "r"(dst_smem), "l"(src));
}
__device__ __forceinline__ void cp_commit() { asm volatile("cp.async.commit_group;"); }
template <int N>
__device__ __forceinline__ void cp_wait() { asm volatile("cp.async.wait_group %0;" :: "n"(N)); }

// ---------------------------------------------------------------------------
// Merged pre-pass: router (blocks [0, NTOK/8)) + W fp32->fp16 (rest).
// ---------------------------------------------------------------------------
#define NW4 ((NEXP * D_MODEL * D_MODEL) / 4)
#define ROUTER_BLOCKS (NTOK / 8)            // 2048: 8 tokens (warps) per block
#define CONV_BLOCKS ((3 * NW4) / 512)       // 6144: 2 float4 per thread
#define PRE_BLOCKS (ROUTER_BLOCKS + CONV_BLOCKS)

__device__ __forceinline__ void conv_one(int j, const float4* Wg, const float4* Wv,
                                         const float4* Wd) {
    const float4* src;
    __half2* dst;
    int off;
    if (j < NW4) {
        src = Wg;  dst = (__half2*)g_wh;               off = j;
    } else if (j < 2 * NW4) {
        src = Wv;  dst = (__half2*)g_wh + 2 * NW4;     off = j - NW4;
    } else {
        src = Wd;  dst = (__half2*)g_wh + 4 * NW4;     off = j - 2 * NW4;
    }
    float4 v = src[off];
    dst[2 * off]     = __floats2half2_rn(v.x, v.y);
    dst[2 * off + 1] = __floats2half2_rn(v.z, v.w);
}

__global__ __launch_bounds__(256) void prepass_kernel(
    const float* __restrict__ x, const float* __restrict__ Wgate,
    const float4* __restrict__ Wg, const float4* __restrict__ Wv,
    const float4* __restrict__ Wd)
{
    if (blockIdx.x >= ROUTER_BLOCKS) {
        int j0 = (blockIdx.x - ROUTER_BLOCKS) * 512 + threadIdx.x;
        conv_one(j0, Wg, Wv, Wd);
        conv_one(j0 + 256, Wg, Wv, Wd);
        return;
    }
    // ---- router part: one warp per token, float4-vectorized ----
    int gtid  = blockIdx.x * 256 + threadIdx.x;
    int token = gtid >> 5;
    int lane  = gtid & 31;
    const float4* x4 = (const float4*)(x + (size_t)token * D_MODEL);
    __half2* xo2 = (__half2*)(g_xh + (size_t)token * D_MODEL);
    const float4* W0 = (const float4*)Wgate;
    const float4* W1 = (const float4*)(Wgate + D_MODEL);
    const float4* W2 = (const float4*)(Wgate + 2 * D_MODEL);
    const float4* W3 = (const float4*)(Wgate + 3 * D_MODEL);

    float a0 = 0.f, a1 = 0.f, a2 = 0.f, a3 = 0.f;
    #pragma unroll
    for (int k4 = lane; k4 < D_MODEL / 4; k4 += 32) {
        float4 xv = x4[k4];
        xo2[2 * k4]     = __floats2half2_rn(xv.x, xv.y);
        xo2[2 * k4 + 1] = __floats2half2_rn(xv.z, xv.w);
        float4 w;
        w = W0[k4];
        a0 = fmaf(xv.x, w.x, fmaf(xv.y, w.y, fmaf(xv.z, w.z, fmaf(xv.w, w.w, a0))));
        w = W1[k4];
        a1 = fmaf(xv.x, w.x, fmaf(xv.y, w.y, fmaf(xv.z, w.z, fmaf(xv.w, w.w, a1))));
        w = W2[k4];
        a2 = fmaf(xv.x, w.x, fmaf(xv.y, w.y, fmaf(xv.z, w.z, fmaf(xv.w, w.w, a2))));
        w = W3[k4];
        a3 = fmaf(xv.x, w.x, fmaf(xv.y, w.y, fmaf(xv.z, w.z, fmaf(xv.w, w.w, a3))));
    }
    #pragma unroll
    for (int o = 16; o; o >>= 1) {
        a0 += __shfl_down_sync(0xffffffffu, a0, o);
        a1 += __shfl_down_sync(0xffffffffu, a1, o);
        a2 += __shfl_down_sync(0xffffffffu, a2, o);
        a3 += __shfl_down_sync(0xffffffffu, a3, o);
    }
    if (lane == 0) {
        float l[4] = {a0, a1, a2, a3};
        int i0 = 0;
        #pragma unroll
        for (int i = 1; i < 4; i++) if (l[i] > l[i0]) i0 = i;
        int i1 = -1;
        #pragma unroll
        for (int i = 0; i < 4; i++) if (i != i0 && (i1 < 0 || l[i] > l[i1])) i1 = i;
        float ex = __expf(l[i1] - l[i0]);
        float den = 1.0f + ex;
        float wv[4] = {0.f, 0.f, 0.f, 0.f};
        wv[i0] = 1.0f / den;
        wv[i1] = ex / den;
        *(float4*)(g_w + (size_t)token * NEXP) = make_float4(wv[0], wv[1], wv[2], wv[3]);
    }
}

// ---------------------------------------------------------------------------
// Fused projection GEMM: fp16 mma.m16n8k16 + ldmatrix, 3-stage cp.async
// pipeline, single __syncthreads per stage. CTA 256(M) x 64(N) x 3 matrices,
// 512 threads, 16 warps = 4(M) x 4(N). Epilogue: activations -> interleaved
// (a,x) + per-32-token scan summaries stored directly (no shuffle combine).
// ---------------------------------------------------------------------------
__global__ __launch_bounds__(512, 1) void proj_gemm_kernel(
    const float* __restrict__ bg, const float* __restrict__ bv,
    const float* __restrict__ bd)
{
    extern __shared__ char smem[];
    const uint32_t sbase = (uint32_t)__cvta_generic_to_shared(smem);

    const int e     = blockIdx.z;
    const int mBase = blockIdx.x * BM;
    const int nBase = blockIdx.y * BN;

    const int tid  = threadIdx.x;
    const int wid  = tid >> 5, lane = tid & 31;
    const int wm   = wid >> 2, wn = wid & 3;   // 4(M) x 4(N)
    const int grp  = lane >> 2, qid = lane & 3;

    const __half* xh = g_xh;
    const __half* wmat[3] = {
        g_wh + (size_t)0 * NEXP * D_MODEL * D_MODEL + (size_t)e * D_MODEL * D_MODEL,
        g_wh + (size_t)1 * NEXP * D_MODEL * D_MODEL + (size_t)e * D_MODEL * D_MODEL,
        g_wh + (size_t)2 * NEXP * D_MODEL * D_MODEL + (size_t)e * D_MODEL * D_MODEL };

    const int rA = wm * 64 + ((lane >> 3) & 1) * 8 + (lane & 7);
    const int kA = (lane >> 4) * 16;
    const int rB = wn * 16 + ((lane >> 4) & 1) * 8 + (lane & 7);
    const int kB = ((lane >> 3) & 1) * 16;

    const uint32_t addrA0 = sbase + (uint32_t)rA * PITCH + kA;
    const uint32_t addrB0 = sbase + (uint32_t)(AROWS + rB) * PITCH + kB;

    float acc[3][4][2][4];
    #pragma unroll
    for (int m = 0; m < 3; m++)
        #pragma unroll
        for (int i = 0; i < 4; i++)
            #pragma unroll
            for (int j = 0; j < 2; j++)
                #pragma unroll
                for (int r = 0; r < 4; r++) acc[m][i][j][r] = 0.f;

    // producer: 448 rows x 8 chunks = 3584 chunks per stage, 7 per thread
    auto load_stage = [&](int kb, int st) {
        const uint32_t dst0 = sbase + st * STG_BYTES;
        const int kcol = kb * BKH;
        #pragma unroll
        for (int it = 0; it < 7; it++) {
            int cid = tid + it * 512;
            int row = cid >> 3, c = cid & 7;
            const __half* src;
            if (row < AROWS) {
                src = xh + (size_t)(mBase + row) * D_MODEL + kcol + c * 8;
            } else {
                int r2 = row - AROWS;
                src = wmat[r2 >> 6] + (size_t)(nBase + (r2 & 63)) * D_MODEL + kcol + c * 8;
            }
            cpasync16(dst0 + (uint32_t)row * PITCH + c * 16, src);
        }
    };

    load_stage(0, 0);
    cp_commit();
    load_stage(1, 1);
    cp_commit();

    int st = 0;                      // stage buffer index = kb % 3
    for (int kb = 0; kb < NKB; kb++) {
        if (kb < NKB - 1) cp_wait<1>(); else cp_wait<0>();
        __syncthreads();
        if (kb + 2 < NKB) {
            int st2 = st + 2; if (st2 >= NSTG) st2 -= NSTG;
            load_stage(kb + 2, st2);
            cp_commit();
        }

        const uint32_t stoff = (uint32_t)st * STG_BYTES;
        const uint32_t aA = addrA0 + stoff;
        const uint32_t aB = addrB0 + stoff;

        #pragma unroll
        for (int s = 0; s < 4; s++) {
            uint32_t af[4][4];
            #pragma unroll
            for (int i = 0; i < 4; i++)
                ldsm4(af[i], aA + i * (16 * PITCH) + s * 32);
            #pragma unroll
            for (int m = 0; m < 3; m++) {
                uint32_t bf[4];
                ldsm4(bf, aB + m * (64 * PITCH) + s * 32);
                #pragma unroll
                for (int j = 0; j < 2; j++)
                    #pragma unroll
                    for (int i = 0; i < 4; i++)
                        mma_f16(acc[m][i][j], af[i], bf + 2 * j);
            }
        }
        if (++st == NSTG) st = 0;
    }
    // Protect stage-smem reuse by the epilogue scan buffer.
    __syncthreads();
    __half2* buf = (__half2*)(smem + wid * 4096);   // 16 warps x 4 KB = 64 KB

    // ---- fused epilogue: activations -> interleaved (a,x) + smem tile ----
    const float* bias0 = bg + e * D_MODEL;
    const float* bias1 = bv + e * D_MODEL;
    const float* bias2 = bd + e * D_MODEL;
    #pragma unroll
    for (int i = 0; i < 4; i++)
        #pragma unroll
        for (int j = 0; j < 2; j++)
            #pragma unroll
            for (int h = 0; h < 2; h++) {
                int tloc = i * 16 + h * 8 + grp;             // 0..63 within chunk
                int cloc = j * 8 + qid * 2;                  // 0..14 within warp cols
                int row = mBase + wm * 64 + tloc;
                int col = nBase + wn * 16 + cloc;
                float g0 = acc[0][i][j][h * 2 + 0] + __ldg(bias0 + col);
                float g1 = acc[0][i][j][h * 2 + 1] + __ldg(bias0 + col + 1);
                float v0 = acc[1][i][j][h * 2 + 0] + __ldg(bias1 + col);
                float v1 = acc[1][i][j][h * 2 + 1] + __ldg(bias1 + col + 1);
                float d0 = acc[2][i][j][h * 2 + 0] + __ldg(bias2 + col);
                float d1 = acc[2][i][j][h * 2 + 1] + __ldg(bias2 + col + 1);
                float xs0 = sigmoid_acc(g0) * tanh_acc(v0);
                float xs1 = sigmoid_acc(g1) * tanh_acc(v1);
                float av0 = 0.001f + 0.998f * sigmoid_acc(d0);
                float av1 = 0.001f + 0.998f * sigmoid_acc(d1);
                __half2 xsh = __floats2half2_rn(xs0, xs1);
                __half2 avh = __floats2half2_rn(av0, av1);
                size_t base = ((size_t)e * NTOK + row) * D_MODEL + col;
                uint2 pr;
                pr.x = *reinterpret_cast<uint32_t*>(&avh);
                pr.y = *reinterpret_cast<uint32_t*>(&xsh);
                g_ax[base >> 1] = pr;
                buf[tloc * 16 + cloc]     = __floats2half2_rn(av0, xs0);
                buf[tloc * 16 + cloc + 1] = __floats2half2_rn(av1, xs1);
            }
    __syncwarp();

    // ---- fused sub-chunk (32 t) summary scan: 2 lanes per column ----
    // Each lane-pair half stores its own 32-token summary directly; the
    // cross-sub-chunk composition happens in scan_pass2 at 32-granularity.
    {
        int col = lane >> 1;           // 0..15
        int tp  = lane & 1;            // sub-chunk selector within the 64-chunk
        int t0  = tp * 32;
        float A = 1.f, X = 0.f;
        #pragma unroll 8
        for (int t = 0; t < 32; t++) {
            float2 ax = __half22float2(buf[(t0 + t) * 16 + col]);
            X = fmaf(ax.x, X, ax.y);
            A *= ax.x;
        }
        int row0 = mBase + wm * 64;               // 64-chunk start token
        int b    = row0 >> 12;                    // / S_LEN
        int sc   = ((row0 & (S_LEN - 1)) >> 5) + tp;  // sub-chunk 0..127
        int eb   = e * BATCH + b;
        int gcol = nBase + wn * 16 + col;
        g_sumAX[(eb * NCHUNK2 + sc) * D_MODEL + gcol] = make_float2(A, X);
    }
}

// ---------------------------------------------------------------------------
// Serial prefix over 128 sub-chunks (MLP-16 prefetch)
// ---------------------------------------------------------------------------
__global__ __launch_bounds__(256) void scan_pass2() {
    int idx = blockIdx.x * 256 + threadIdx.x;
    int eb = idx >> 10, d = idx & 1023;
    const float2* s = g_sumAX + (size_t)eb * NCHUNK2 * D_MODEL + d;
    float* hs = g_hstart + (size_t)eb * NCHUNK2 * D_MODEL + d;
    float h = 0.f;
    #pragma unroll
    for (int c = 0; c < NCHUNK2; c += 16) {
        float2 sv[16];
        #pragma unroll
        for (int u = 0; u < 16; u++) sv[u] = s[(c + u) * D_MODEL];
        #pragma unroll
        for (int u = 0; u < 16; u++) {
            hs[(c + u) * D_MODEL] = h;
            h = fmaf(sv[u].x, h, sv[u].y);
        }
    }
}

// ---------------------------------------------------------------------------
// Re-scan each 32-token sub-chunk with correct start state + router combine.
// 4 channels/thread (uint4), t+1 prefetch, grid 1024 blocks of 128.
// ---------------------------------------------------------------------------
__global__ __launch_bounds__(128) void scan_pass3(float* __restrict__ out) {
    int d4 = blockIdx.x * 128 + threadIdx.x;        // channel quad 0..255
    int c  = blockIdx.y;                            // sub-chunk 0..127
    int b  = blockIdx.z;
    __shared__ float ws[CHUNK2 * NEXP];             // 128 floats
    int t0 = c * CHUNK2;
    ws[threadIdx.x] = g_w[(size_t)(b * S_LEN + t0) * NEXP + threadIdx.x];
    __syncthreads();

    float4 h[NEXP];
    const uint4* axp[NEXP];
    #pragma unroll
    for (int e = 0; e < NEXP; e++) {
        int eb = e * BATCH + b;
        h[e] = *(const float4*)(g_hstart + ((size_t)eb * NCHUNK2 + c) * D_MODEL + 4 * d4);
        axp[e] = (const uint4*)g_ax + ((size_t)(eb * S_LEN + t0) * (D_MODEL / 4) + d4);
    }
    float* op = out + ((size_t)(b * S_LEN + t0)) * D_MODEL + 4 * d4;

    uint4 v[NEXP];
    #pragma unroll
    for (int e = 0; e < NEXP; e++) v[e] = axp[e][0];

    #pragma unroll 4
    for (int t = 0; t < CHUNK2; t++) {
        uint4 vn[NEXP];
        if (t + 1 < CHUNK2) {
            #pragma unroll
            for (int e = 0; e < NEXP; e++)
                vn[e] = axp[e][(size_t)(t + 1) * (D_MODEL / 4)];
        }
        float4 acc = make_float4(0.f, 0.f, 0.f, 0.f);
        #pragma unroll
        for (int e = 0; e < NEXP; e++) {
            float2 a01 = __half22float2(*reinterpret_cast<__half2*>(&v[e].x));
            float2 x01 = __half22float2(*reinterpret_cast<__half2*>(&v[e].y));
            float2 a23 = __half22float2(*reinterpret_cast<__half2*>(&v[e].z));
            float2 x23 = __half22float2(*reinterpret_cast<__half2*>(&v[e].w));
            h[e].x = fmaf(a01.x, h[e].x, x01.x);
            h[e].y = fmaf(a01.y, h[e].y, x01.y);
            h[e].z = fmaf(a23.x, h[e].z, x23.x);
            h[e].w = fmaf(a23.y, h[e].w, x23.y);
            float w = ws[t * NEXP + e];
            acc.x = fmaf(w, h[e].x, acc.x);
            acc.y = fmaf(w, h[e].y, acc.y);
            acc.z = fmaf(w, h[e].z, acc.z);
            acc.w = fmaf(w, h[e].w, acc.w);
        }
        *(float4*)(op + (size_t)t * D_MODEL) = acc;
        #pragma unroll
        for (int e = 0; e < NEXP; e++) v[e] = vn[e];
    }
}

// ---------------------------------------------------------------------------
// Launch
// ---------------------------------------------------------------------------
extern "C" void kernel_launch(void* const* d_in, const int* in_sizes, int n_in,
                              void* d_out, int out_size) {
    const float* x     = (const float*)d_in[0];
    const float* Wg    = (const float*)d_in[1];
    const float* bg    = (const float*)d_in[2];
    const float* Wv    = (const float*)d_in[3];
    const float* bv    = (const float*)d_in[4];
    const float* Wd    = (const float*)d_in[5];
    const float* bd    = (const float*)d_in[6];
    const float* Wgate = (const float*)d_in[7];
    float* out = (float*)d_out;

    cudaFuncSetAttribute(proj_gemm_kernel,
                         cudaFuncAttributeMaxDynamicSharedMemorySize, SMEM_BYTES);

    // Merged router + W fp32->fp16 conversion
    prepass_kernel<<<PRE_BLOCKS, 256>>>(x, Wgate, (const float4*)Wg,
                                        (const float4*)Wv, (const float4*)Wd);

    proj_gemm_kernel<<<dim3(NTOK / BM, D_MODEL / BN, NEXP), 512, SMEM_BYTES>>>(bg, bv, bd);

    scan_pass2<<<(NEXP * BATCH * D_MODEL) / 256, 256>>>();
    scan_pass3<<<dim3(D_MODEL / 4 / 128, NCHUNK2, BATCH), 128>>>(out);
}